// round 3
// baseline (speedup 1.0000x reference)
#include <cuda_runtime.h>

#define N_NODES 50000
#define F 128
#define NOUT2 32
#define NE 800000

// ---------------- scratch (device globals: no allocation allowed) ----------
__device__ __align__(16) float g_y1[N_NODES * F];       // x @ W1
__device__ __align__(16) float g_h1[N_NODES * F];       // layer-1 activations
__device__ __align__(16) float g_y2[N_NODES * NOUT2];   // h1 @ W2
__device__ int g_eidx[2 * NE];                          // int32 edges (src | dst)
__device__ int g_csr[NE];                               // src lists grouped by dst
__device__ int g_rowptr[N_NODES + 1];
__device__ int g_cur[N_NODES];
__device__ int g_degi[N_NODES];
__device__ int g_is64;

// ---------------- edge dtype detection (int64 vs int32) --------------------
__global__ void detect_kernel(const int* e32) {
    if (threadIdx.x == 0) {
        int is64 = 1;
        #pragma unroll
        for (int i = 0; i < 32; ++i)
            if (e32[2 * i + 1] != 0) { is64 = 0; break; }
        g_is64 = is64;
    }
}

__global__ void zerodeg_kernel() {
    int i = blockIdx.x * blockDim.x + threadIdx.x;
    if (i < N_NODES) g_degi[i] = 0;
}

// ---------------- convert edges to int32 + degree histogram ----------------
__global__ void convert_kernel(const void* __restrict__ edges) {
    int i = blockIdx.x * blockDim.x + threadIdx.x;
    if (i >= 2 * NE) return;
    int v;
    if (g_is64) v = (int)((const long long*)edges)[i];
    else        v = ((const int*)edges)[i];
    g_eidx[i] = v;
    if (i >= NE) atomicAdd(&g_degi[v], 1);   // dst half -> in-degree
}

// ---------------- exclusive prefix sum over degrees (one block) ------------
#define SCAN_T 1024
#define STRIP  ((N_NODES + SCAN_T - 1) / SCAN_T)   // 49
__global__ void scan_kernel() {
    __shared__ int ssum[SCAN_T];
    int t = threadIdx.x;
    int beg = t * STRIP;
    int end = min(beg + STRIP, N_NODES);
    int s = 0;
    for (int i = beg; i < end; ++i) s += g_degi[i];
    ssum[t] = s;
    __syncthreads();
    // Hillis-Steele inclusive scan
    for (int off = 1; off < SCAN_T; off <<= 1) {
        int v = (t >= off) ? ssum[t - off] : 0;
        __syncthreads();
        ssum[t] += v;
        __syncthreads();
    }
    int base = ssum[t] - s;   // exclusive prefix of this strip
    for (int i = beg; i < end; ++i) {
        g_rowptr[i] = base;
        g_cur[i]    = base;
        base += g_degi[i];
    }
    if (t == 0) g_rowptr[N_NODES] = NE;
}

// ---------------- CSR fill --------------------------------------------------
__global__ void fill_kernel() {
    int e = blockIdx.x * blockDim.x + threadIdx.x;
    if (e >= NE) return;
    int s = g_eidx[e];
    int d = g_eidx[NE + e];
    int pos = atomicAdd(&g_cur[d], 1);
    g_csr[pos] = s;
}

// ---------------- GEMM1: y1 = x @ W1 ---------------------------------------
// 256 threads, 32 rows x 128 cols per block, W staged in 32-k chunks.
__global__ __launch_bounds__(256, 4) void gemm1_kernel(
        const float* __restrict__ x, const float* __restrict__ Wg) {
    __shared__ float Xs[32][F + 4];    // 16.9 KB
    __shared__ float Wc[32][F];        // 16 KB chunk

    int t = threadIdx.x;
    int row0 = blockIdx.x * 32;

    // X tile: 32 rows x 32 float4 (4 per thread)
    for (int i = t; i < 32 * 32; i += 256) {
        int r = i >> 5, k4 = i & 31;
        int row = row0 + r;
        float4 v = make_float4(0.f, 0.f, 0.f, 0.f);
        if (row < N_NODES) v = ((const float4*)(x + (size_t)row * F))[k4];
        *(float4*)&Xs[r][k4 * 4] = v;
    }

    int tc = t & 31;      // 32 col-groups of 4  (uniform X addr per warp)
    int tr = t >> 5;      // 8 row-groups of 4

    float acc[4][4];
    #pragma unroll
    for (int r = 0; r < 4; ++r)
        #pragma unroll
        for (int c = 0; c < 4; ++c) acc[r][c] = 0.f;

    for (int kc = 0; kc < 4; ++kc) {
        __syncthreads();
        // W chunk: rows kc*32 .. kc*32+31
        for (int i = t; i < 32 * 32; i += 256) {
            int r = i >> 5, c4 = i & 31;
            *(float4*)&Wc[r][c4 * 4] =
                ((const float4*)(Wg + (size_t)(kc * 32 + r) * F))[c4];
        }
        __syncthreads();

        #pragma unroll
        for (int kk4 = 0; kk4 < 8; ++kk4) {
            float wv[4][4];
            #pragma unroll
            for (int j = 0; j < 4; ++j) {
                float4 q = *(const float4*)&Wc[kk4 * 4 + j][tc * 4];
                wv[j][0] = q.x; wv[j][1] = q.y; wv[j][2] = q.z; wv[j][3] = q.w;
            }
            float xr[4][4];
            #pragma unroll
            for (int r = 0; r < 4; ++r) {
                float4 q = *(const float4*)&Xs[tr * 4 + r][kc * 32 + kk4 * 4];
                xr[r][0] = q.x; xr[r][1] = q.y; xr[r][2] = q.z; xr[r][3] = q.w;
            }
            #pragma unroll
            for (int j = 0; j < 4; ++j)
                #pragma unroll
                for (int r = 0; r < 4; ++r) {
                    acc[r][0] += xr[r][j] * wv[j][0];
                    acc[r][1] += xr[r][j] * wv[j][1];
                    acc[r][2] += xr[r][j] * wv[j][2];
                    acc[r][3] += xr[r][j] * wv[j][3];
                }
        }
    }

    #pragma unroll
    for (int r = 0; r < 4; ++r) {
        int row = row0 + tr * 4 + r;
        if (row < N_NODES) {
            float4 o = make_float4(acc[r][0], acc[r][1], acc[r][2], acc[r][3]);
            ((float4*)(g_y1 + (size_t)row * F))[tc] = o;
        }
    }
}

// ---------------- agg1: h1 = leaky((sum_nbr y1 + y1) * rinv + b1) ----------
// warp per node, 128-wide rows, atomic-free.
__global__ void agg1_kernel(const float* __restrict__ b1g) {
    int w = (blockIdx.x * blockDim.x + threadIdx.x) >> 5;
    if (w >= N_NODES) return;
    int lane = threadIdx.x & 31;
    const float4* Y = (const float4*)g_y1;

    float4 a0 = Y[(size_t)w * 32 + lane];   // self term
    float4 a1 = make_float4(0.f, 0.f, 0.f, 0.f);

    int beg = g_rowptr[w], end = g_rowptr[w + 1];
    int j = beg;
    for (; j + 2 <= end; j += 2) {
        int s0 = g_csr[j], s1 = g_csr[j + 1];
        float4 v0 = Y[(size_t)s0 * 32 + lane];
        float4 v1 = Y[(size_t)s1 * 32 + lane];
        a0.x += v0.x; a0.y += v0.y; a0.z += v0.z; a0.w += v0.w;
        a1.x += v1.x; a1.y += v1.y; a1.z += v1.z; a1.w += v1.w;
    }
    if (j < end) {
        int s = g_csr[j];
        float4 v = Y[(size_t)s * 32 + lane];
        a0.x += v.x; a0.y += v.y; a0.z += v.z; a0.w += v.w;
    }

    float rinv = 1.0f / (float)(end - beg + 1);
    float4 b = ((const float4*)b1g)[lane];
    float4 h;
    h.x = (a0.x + a1.x) * rinv + b.x;
    h.y = (a0.y + a1.y) * rinv + b.y;
    h.z = (a0.z + a1.z) * rinv + b.z;
    h.w = (a0.w + a1.w) * rinv + b.w;
    h.x = h.x >= 0.f ? h.x : 0.01f * h.x;
    h.y = h.y >= 0.f ? h.y : 0.01f * h.y;
    h.z = h.z >= 0.f ? h.z : 0.01f * h.z;
    h.w = h.w >= 0.f ? h.w : 0.01f * h.w;
    ((float4*)g_h1)[(size_t)w * 32 + lane] = h;
}

// ---------------- GEMM2: y2 = h1 @ W2 --------------------------------------
// 256 threads, 64 rows x 32 cols per block.
__global__ __launch_bounds__(256, 4) void gemm2_kernel(
        const float* __restrict__ Wg) {
    __shared__ float Xs[64][F + 4];     // 33.8 KB
    __shared__ float Ws[F][NOUT2];      // 16 KB

    int t = threadIdx.x;
    int row0 = blockIdx.x * 64;

    for (int i = t; i < F * NOUT2 / 4; i += 256) {
        int r = i >> 3, c4 = i & 7;
        *(float4*)&Ws[r][c4 * 4] = ((const float4*)(Wg + (size_t)r * NOUT2))[c4];
    }
    for (int i = t; i < 64 * 32; i += 256) {
        int r = i >> 5, k4 = i & 31;
        int row = row0 + r;
        float4 v = make_float4(0.f, 0.f, 0.f, 0.f);
        if (row < N_NODES) v = ((const float4*)(g_h1 + (size_t)row * F))[k4];
        *(float4*)&Xs[r][k4 * 4] = v;
    }
    __syncthreads();

    int tc = t & 7;     // 8 col-groups of 4
    int tr = t >> 3;    // 32 row-groups of 2

    float acc[2][4];
    #pragma unroll
    for (int r = 0; r < 2; ++r)
        #pragma unroll
        for (int c = 0; c < 4; ++c) acc[r][c] = 0.f;

    #pragma unroll 8
    for (int kk4 = 0; kk4 < F / 4; ++kk4) {
        float wv[4][4];
        #pragma unroll
        for (int j = 0; j < 4; ++j) {
            float4 q = *(const float4*)&Ws[kk4 * 4 + j][tc * 4];
            wv[j][0] = q.x; wv[j][1] = q.y; wv[j][2] = q.z; wv[j][3] = q.w;
        }
        float xr[2][4];
        #pragma unroll
        for (int r = 0; r < 2; ++r) {
            float4 q = *(const float4*)&Xs[tr * 2 + r][kk4 * 4];
            xr[r][0] = q.x; xr[r][1] = q.y; xr[r][2] = q.z; xr[r][3] = q.w;
        }
        #pragma unroll
        for (int j = 0; j < 4; ++j)
            #pragma unroll
            for (int r = 0; r < 2; ++r) {
                acc[r][0] += xr[r][j] * wv[j][0];
                acc[r][1] += xr[r][j] * wv[j][1];
                acc[r][2] += xr[r][j] * wv[j][2];
                acc[r][3] += xr[r][j] * wv[j][3];
            }
    }

    #pragma unroll
    for (int r = 0; r < 2; ++r) {
        int row = row0 + tr * 2 + r;
        if (row < N_NODES) {
            float4 o = make_float4(acc[r][0], acc[r][1], acc[r][2], acc[r][3]);
            ((float4*)(g_y2 + (size_t)row * NOUT2))[tc] = o;
        }
    }
}

// ---------------- agg2: out = (sum_nbr y2 + y2) * rinv + b2 ----------------
// 8 lanes per node, 4 nodes per warp.
__global__ void agg2_kernel(const float* __restrict__ b2g,
                            float* __restrict__ out) {
    int gw = (blockIdx.x * blockDim.x + threadIdx.x) >> 5;
    int lane = threadIdx.x & 31;
    int node = gw * 4 + (lane >> 3);
    if (node >= N_NODES) return;
    int l8 = lane & 7;
    const float4* Y = (const float4*)g_y2;

    float4 a0 = Y[(size_t)node * 8 + l8];   // self
    float4 a1 = make_float4(0.f, 0.f, 0.f, 0.f);

    int beg = g_rowptr[node], end = g_rowptr[node + 1];
    int j = beg;
    for (; j + 2 <= end; j += 2) {
        int s0 = g_csr[j], s1 = g_csr[j + 1];
        float4 v0 = Y[(size_t)s0 * 8 + l8];
        float4 v1 = Y[(size_t)s1 * 8 + l8];
        a0.x += v0.x; a0.y += v0.y; a0.z += v0.z; a0.w += v0.w;
        a1.x += v1.x; a1.y += v1.y; a1.z += v1.z; a1.w += v1.w;
    }
    if (j < end) {
        int s = g_csr[j];
        float4 v = Y[(size_t)s * 8 + l8];
        a0.x += v.x; a0.y += v.y; a0.z += v.z; a0.w += v.w;
    }

    float rinv = 1.0f / (float)(end - beg + 1);
    float4 b = ((const float4*)b2g)[l8];
    float4 o;
    o.x = (a0.x + a1.x) * rinv + b.x;
    o.y = (a0.y + a1.y) * rinv + b.y;
    o.z = (a0.z + a1.z) * rinv + b.z;
    o.w = (a0.w + a1.w) * rinv + b.w;
    ((float4*)(out + (size_t)node * NOUT2))[l8] = o;
}

// ---------------- launch ----------------------------------------------------
extern "C" void kernel_launch(void* const* d_in, const int* in_sizes, int n_in,
                              void* d_out, int out_size) {
    const float* in_feat = (const float*)d_in[0];
    const void*  edges   = d_in[1];
    const float* W1      = (const float*)d_in[2];
    const float* b1      = (const float*)d_in[3];
    const float* W2      = (const float*)d_in[4];
    const float* b2      = (const float*)d_in[5];
    float* out = (float*)d_out;

    detect_kernel<<<1, 32>>>((const int*)edges);
    zerodeg_kernel<<<(N_NODES + 255) / 256, 256>>>();
    convert_kernel<<<(2 * NE + 255) / 256, 256>>>(edges);
    scan_kernel<<<1, SCAN_T>>>();
    fill_kernel<<<(NE + 255) / 256, 256>>>();

    gemm1_kernel<<<(N_NODES + 31) / 32, 256>>>(in_feat, W1);
    agg1_kernel<<<(N_NODES * 32 + 255) / 256, 256>>>(b1);      // warp/node
    gemm2_kernel<<<(N_NODES + 63) / 64, 256>>>(W2);
    agg2_kernel<<<((N_NODES + 3) / 4 * 32 + 255) / 256, 256>>>(b2, out);
}

// round 4
// speedup vs baseline: 1.4865x; 1.4865x over previous
#include <cuda_runtime.h>

#define N_NODES 50000
#define F 128
#define NOUT2 32
#define NE 800000

#define SCAN_BS 256
#define SCAN_NB ((N_NODES + SCAN_BS - 1) / SCAN_BS)   // 196

// ---------------- scratch (device globals: no allocation allowed) ----------
__device__ __align__(16) float g_y1[N_NODES * F];       // x @ W1
__device__ __align__(16) float g_h1[N_NODES * F];       // layer-1 activations
__device__ __align__(16) float g_y2[N_NODES * NOUT2];   // h1 @ W2
__device__ int g_eidx[2 * NE];                          // int32 edges (src | dst)
__device__ int g_csr[NE];                               // src lists grouped by dst
__device__ int g_rowptr[N_NODES + 1];
__device__ int g_cur[N_NODES];
__device__ int g_degi[N_NODES];
__device__ int g_bsum[SCAN_NB];
__device__ int g_boff[SCAN_NB];
__device__ int g_is64;

// ---------------- edge dtype detection (int64 vs int32) --------------------
__global__ void detect_kernel(const int* e32) {
    if (threadIdx.x == 0) {
        int is64 = 1;
        #pragma unroll
        for (int i = 0; i < 32; ++i)
            if (e32[2 * i + 1] != 0) { is64 = 0; break; }
        g_is64 = is64;
    }
}

__global__ void zerodeg_kernel() {
    int i = blockIdx.x * blockDim.x + threadIdx.x;
    if (i < N_NODES) g_degi[i] = 0;
}

// ---------------- convert edges to int32 + degree histogram ----------------
__global__ void convert_kernel(const void* __restrict__ edges) {
    int i = blockIdx.x * blockDim.x + threadIdx.x;
    if (i >= 2 * NE) return;
    int v;
    if (g_is64) v = (int)((const long long*)edges)[i];
    else        v = ((const int*)edges)[i];
    g_eidx[i] = v;
    if (i >= NE) atomicAdd(&g_degi[v], 1);   // dst half -> in-degree
}

// ---------------- hierarchical exclusive scan over degrees -----------------
// phase 1: per-block sums
__global__ void scan1_kernel() {
    __shared__ int wsum[8];
    int i = blockIdx.x * SCAN_BS + threadIdx.x;
    int v = (i < N_NODES) ? g_degi[i] : 0;
    #pragma unroll
    for (int off = 16; off > 0; off >>= 1)
        v += __shfl_down_sync(0xffffffffu, v, off);
    if ((threadIdx.x & 31) == 0) wsum[threadIdx.x >> 5] = v;
    __syncthreads();
    if (threadIdx.x < 8) {
        int s = wsum[threadIdx.x];
        #pragma unroll
        for (int off = 4; off > 0; off >>= 1)
            s += __shfl_down_sync(0xffu, s, off);
        if (threadIdx.x == 0) g_bsum[blockIdx.x] = s;
    }
}

// phase 2: scan block sums (one block, 256 threads >= 196 entries)
__global__ void scan2_kernel() {
    __shared__ int sh[SCAN_BS];
    int t = threadIdx.x;
    int v = (t < SCAN_NB) ? g_bsum[t] : 0;
    sh[t] = v;
    __syncthreads();
    for (int off = 1; off < SCAN_BS; off <<= 1) {
        int u = (t >= off) ? sh[t - off] : 0;
        __syncthreads();
        sh[t] += u;
        __syncthreads();
    }
    if (t < SCAN_NB) g_boff[t] = sh[t] - v;   // exclusive
    if (t == 0) g_rowptr[N_NODES] = NE;
}

// phase 3: local exclusive scan + block offset -> rowptr, cur
__global__ void scan3_kernel() {
    __shared__ int woff[8];
    int i = blockIdx.x * SCAN_BS + threadIdx.x;
    int lane = threadIdx.x & 31;
    int warp = threadIdx.x >> 5;
    int v = (i < N_NODES) ? g_degi[i] : 0;

    // warp inclusive scan
    int s = v;
    #pragma unroll
    for (int off = 1; off < 32; off <<= 1) {
        int u = __shfl_up_sync(0xffffffffu, s, off);
        if (lane >= off) s += u;
    }
    if (lane == 31) woff[warp] = s;
    __syncthreads();
    if (threadIdx.x < 8) {
        int ws = woff[threadIdx.x];
        #pragma unroll
        for (int off = 1; off < 8; off <<= 1) {
            int u = __shfl_up_sync(0xffu, ws, off);
            if ((int)threadIdx.x >= off) ws += u;
        }
        woff[threadIdx.x] = ws;
    }
    __syncthreads();
    int excl = s - v + (warp > 0 ? woff[warp - 1] : 0) + g_boff[blockIdx.x];
    if (i < N_NODES) {
        g_rowptr[i] = excl;
        g_cur[i]    = excl;
    }
}

// ---------------- CSR fill --------------------------------------------------
__global__ void fill_kernel() {
    int e = blockIdx.x * blockDim.x + threadIdx.x;
    if (e >= NE) return;
    int s = g_eidx[e];
    int d = g_eidx[NE + e];
    int pos = atomicAdd(&g_cur[d], 1);
    g_csr[pos] = s;
}

// ---------------- GEMM1: y1 = x @ W1 ---------------------------------------
// 256 threads, 32 rows x 128 cols per block, W staged in 32-k chunks.
__global__ __launch_bounds__(256, 4) void gemm1_kernel(
        const float* __restrict__ x, const float* __restrict__ Wg) {
    __shared__ float Xs[32][F + 4];    // 16.9 KB
    __shared__ float Wc[32][F];        // 16 KB chunk

    int t = threadIdx.x;
    int row0 = blockIdx.x * 32;

    for (int i = t; i < 32 * 32; i += 256) {
        int r = i >> 5, k4 = i & 31;
        int row = row0 + r;
        float4 v = make_float4(0.f, 0.f, 0.f, 0.f);
        if (row < N_NODES) v = ((const float4*)(x + (size_t)row * F))[k4];
        *(float4*)&Xs[r][k4 * 4] = v;
    }

    int tc = t & 31;      // 32 col-groups of 4
    int tr = t >> 5;      // 8 row-groups of 4

    float acc[4][4];
    #pragma unroll
    for (int r = 0; r < 4; ++r)
        #pragma unroll
        for (int c = 0; c < 4; ++c) acc[r][c] = 0.f;

    for (int kc = 0; kc < 4; ++kc) {
        __syncthreads();
        for (int i = t; i < 32 * 32; i += 256) {
            int r = i >> 5, c4 = i & 31;
            *(float4*)&Wc[r][c4 * 4] =
                ((const float4*)(Wg + (size_t)(kc * 32 + r) * F))[c4];
        }
        __syncthreads();

        #pragma unroll
        for (int kk4 = 0; kk4 < 8; ++kk4) {
            float wv[4][4];
            #pragma unroll
            for (int j = 0; j < 4; ++j) {
                float4 q = *(const float4*)&Wc[kk4 * 4 + j][tc * 4];
                wv[j][0] = q.x; wv[j][1] = q.y; wv[j][2] = q.z; wv[j][3] = q.w;
            }
            float xr[4][4];
            #pragma unroll
            for (int r = 0; r < 4; ++r) {
                float4 q = *(const float4*)&Xs[tr * 4 + r][kc * 32 + kk4 * 4];
                xr[r][0] = q.x; xr[r][1] = q.y; xr[r][2] = q.z; xr[r][3] = q.w;
            }
            #pragma unroll
            for (int j = 0; j < 4; ++j)
                #pragma unroll
                for (int r = 0; r < 4; ++r) {
                    acc[r][0] += xr[r][j] * wv[j][0];
                    acc[r][1] += xr[r][j] * wv[j][1];
                    acc[r][2] += xr[r][j] * wv[j][2];
                    acc[r][3] += xr[r][j] * wv[j][3];
                }
        }
    }

    #pragma unroll
    for (int r = 0; r < 4; ++r) {
        int row = row0 + tr * 4 + r;
        if (row < N_NODES) {
            float4 o = make_float4(acc[r][0], acc[r][1], acc[r][2], acc[r][3]);
            ((float4*)(g_y1 + (size_t)row * F))[tc] = o;
        }
    }
}

// ---------------- agg1: h1 = leaky((sum_nbr y1 + y1) * rinv + b1) ----------
__global__ void agg1_kernel(const float* __restrict__ b1g) {
    int w = (blockIdx.x * blockDim.x + threadIdx.x) >> 5;
    if (w >= N_NODES) return;
    int lane = threadIdx.x & 31;
    const float4* Y = (const float4*)g_y1;

    float4 a0 = Y[(size_t)w * 32 + lane];   // self term
    float4 a1 = make_float4(0.f, 0.f, 0.f, 0.f);

    int beg = g_rowptr[w], end = g_rowptr[w + 1];
    int j = beg;
    for (; j + 2 <= end; j += 2) {
        int s0 = g_csr[j], s1 = g_csr[j + 1];
        float4 v0 = Y[(size_t)s0 * 32 + lane];
        float4 v1 = Y[(size_t)s1 * 32 + lane];
        a0.x += v0.x; a0.y += v0.y; a0.z += v0.z; a0.w += v0.w;
        a1.x += v1.x; a1.y += v1.y; a1.z += v1.z; a1.w += v1.w;
    }
    if (j < end) {
        int s = g_csr[j];
        float4 v = Y[(size_t)s * 32 + lane];
        a0.x += v.x; a0.y += v.y; a0.z += v.z; a0.w += v.w;
    }

    float rinv = 1.0f / (float)(end - beg + 1);
    float4 b = ((const float4*)b1g)[lane];
    float4 h;
    h.x = (a0.x + a1.x) * rinv + b.x;
    h.y = (a0.y + a1.y) * rinv + b.y;
    h.z = (a0.z + a1.z) * rinv + b.z;
    h.w = (a0.w + a1.w) * rinv + b.w;
    h.x = h.x >= 0.f ? h.x : 0.01f * h.x;
    h.y = h.y >= 0.f ? h.y : 0.01f * h.y;
    h.z = h.z >= 0.f ? h.z : 0.01f * h.z;
    h.w = h.w >= 0.f ? h.w : 0.01f * h.w;
    ((float4*)g_h1)[(size_t)w * 32 + lane] = h;
}

// ---------------- GEMM2: y2 = h1 @ W2 --------------------------------------
__global__ __launch_bounds__(256, 4) void gemm2_kernel(
        const float* __restrict__ Wg) {
    __shared__ float Xs[64][F + 4];     // 33.8 KB
    __shared__ float Ws[F][NOUT2];      // 16 KB

    int t = threadIdx.x;
    int row0 = blockIdx.x * 64;

    for (int i = t; i < F * NOUT2 / 4; i += 256) {
        int r = i >> 3, c4 = i & 7;
        *(float4*)&Ws[r][c4 * 4] = ((const float4*)(Wg + (size_t)r * NOUT2))[c4];
    }
    for (int i = t; i < 64 * 32; i += 256) {
        int r = i >> 5, k4 = i & 31;
        int row = row0 + r;
        float4 v = make_float4(0.f, 0.f, 0.f, 0.f);
        if (row < N_NODES) v = ((const float4*)(g_h1 + (size_t)row * F))[k4];
        *(float4*)&Xs[r][k4 * 4] = v;
    }
    __syncthreads();

    int tc = t & 7;     // 8 col-groups of 4
    int tr = t >> 3;    // 32 row-groups of 2

    float acc[2][4];
    #pragma unroll
    for (int r = 0; r < 2; ++r)
        #pragma unroll
        for (int c = 0; c < 4; ++c) acc[r][c] = 0.f;

    #pragma unroll 8
    for (int kk4 = 0; kk4 < F / 4; ++kk4) {
        float wv[4][4];
        #pragma unroll
        for (int j = 0; j < 4; ++j) {
            float4 q = *(const float4*)&Ws[kk4 * 4 + j][tc * 4];
            wv[j][0] = q.x; wv[j][1] = q.y; wv[j][2] = q.z; wv[j][3] = q.w;
        }
        float xr[2][4];
        #pragma unroll
        for (int r = 0; r < 2; ++r) {
            float4 q = *(const float4*)&Xs[tr * 2 + r][kk4 * 4];
            xr[r][0] = q.x; xr[r][1] = q.y; xr[r][2] = q.z; xr[r][3] = q.w;
        }
        #pragma unroll
        for (int j = 0; j < 4; ++j)
            #pragma unroll
            for (int r = 0; r < 2; ++r) {
                acc[r][0] += xr[r][j] * wv[j][0];
                acc[r][1] += xr[r][j] * wv[j][1];
                acc[r][2] += xr[r][j] * wv[j][2];
                acc[r][3] += xr[r][j] * wv[j][3];
            }
    }

    #pragma unroll
    for (int r = 0; r < 2; ++r) {
        int row = row0 + tr * 2 + r;
        if (row < N_NODES) {
            float4 o = make_float4(acc[r][0], acc[r][1], acc[r][2], acc[r][3]);
            ((float4*)(g_y2 + (size_t)row * NOUT2))[tc] = o;
        }
    }
}

// ---------------- agg2: out = (sum_nbr y2 + y2) * rinv + b2 ----------------
__global__ void agg2_kernel(const float* __restrict__ b2g,
                            float* __restrict__ out) {
    int gw = (blockIdx.x * blockDim.x + threadIdx.x) >> 5;
    int lane = threadIdx.x & 31;
    int node = gw * 4 + (lane >> 3);
    if (node >= N_NODES) return;
    int l8 = lane & 7;
    const float4* Y = (const float4*)g_y2;

    float4 a0 = Y[(size_t)node * 8 + l8];   // self
    float4 a1 = make_float4(0.f, 0.f, 0.f, 0.f);

    int beg = g_rowptr[node], end = g_rowptr[node + 1];
    int j = beg;
    for (; j + 2 <= end; j += 2) {
        int s0 = g_csr[j], s1 = g_csr[j + 1];
        float4 v0 = Y[(size_t)s0 * 8 + l8];
        float4 v1 = Y[(size_t)s1 * 8 + l8];
        a0.x += v0.x; a0.y += v0.y; a0.z += v0.z; a0.w += v0.w;
        a1.x += v1.x; a1.y += v1.y; a1.z += v1.z; a1.w += v1.w;
    }
    if (j < end) {
        int s = g_csr[j];
        float4 v = Y[(size_t)s * 8 + l8];
        a0.x += v.x; a0.y += v.y; a0.z += v.z; a0.w += v.w;
    }

    float rinv = 1.0f / (float)(end - beg + 1);
    float4 b = ((const float4*)b2g)[l8];
    float4 o;
    o.x = (a0.x + a1.x) * rinv + b.x;
    o.y = (a0.y + a1.y) * rinv + b.y;
    o.z = (a0.z + a1.z) * rinv + b.z;
    o.w = (a0.w + a1.w) * rinv + b.w;
    ((float4*)(out + (size_t)node * NOUT2))[l8] = o;
}

// ---------------- launch ----------------------------------------------------
extern "C" void kernel_launch(void* const* d_in, const int* in_sizes, int n_in,
                              void* d_out, int out_size) {
    const float* in_feat = (const float*)d_in[0];
    const void*  edges   = d_in[1];
    const float* W1      = (const float*)d_in[2];
    const float* b1      = (const float*)d_in[3];
    const float* W2      = (const float*)d_in[4];
    const float* b2      = (const float*)d_in[5];
    float* out = (float*)d_out;

    detect_kernel<<<1, 32>>>((const int*)edges);
    zerodeg_kernel<<<(N_NODES + 255) / 256, 256>>>();
    convert_kernel<<<(2 * NE + 255) / 256, 256>>>(edges);
    scan1_kernel<<<SCAN_NB, SCAN_BS>>>();
    scan2_kernel<<<1, SCAN_BS>>>();
    scan3_kernel<<<SCAN_NB, SCAN_BS>>>();
    fill_kernel<<<(NE + 255) / 256, 256>>>();

    gemm1_kernel<<<(N_NODES + 31) / 32, 256>>>(in_feat, W1);
    agg1_kernel<<<(N_NODES * 32 + 255) / 256, 256>>>(b1);      // warp/node
    gemm2_kernel<<<(N_NODES + 63) / 64, 256>>>(W2);
    agg2_kernel<<<((N_NODES + 3) / 4 * 32 + 255) / 256, 256>>>(b2, out);
}

// round 6
// speedup vs baseline: 1.6684x; 1.1224x over previous
#include <cuda_runtime.h>
#include <cuda_bf16.h>
#include <cstdint>

#define N_NODES 50000
#define F 128
#define NOUT2 32
#define NE 800000

#define SCAN_BS 256
#define SCAN_NB ((N_NODES + SCAN_BS - 1) / SCAN_BS)   // 196

// ---------------- scratch (device globals: no allocation allowed) ----------
__device__ __align__(16) float g_y1[N_NODES * F];        // x @ W1 (fp32)
__device__ __align__(16) float g_y2[N_NODES * NOUT2];    // h1 @ W2 (fp32)
__device__ __align__(16) __nv_bfloat16 g_xhi[N_NODES * F];
__device__ __align__(16) __nv_bfloat16 g_xlo[N_NODES * F];
__device__ __align__(16) __nv_bfloat16 g_h1hi[N_NODES * F];
__device__ __align__(16) __nv_bfloat16 g_h1lo[N_NODES * F];
__device__ __align__(16) __nv_bfloat16 g_b1hi[F * F];    // W1^T  [n][k]
__device__ __align__(16) __nv_bfloat16 g_b1lo[F * F];
__device__ __align__(16) __nv_bfloat16 g_b2hi[NOUT2 * F];// W2^T  [n][k]
__device__ __align__(16) __nv_bfloat16 g_b2lo[NOUT2 * F];
__device__ int g_eidx[2 * NE];
__device__ int g_csr[NE];
__device__ int g_rowptr[N_NODES + 1];
__device__ int g_cur[N_NODES];
__device__ int g_degi[N_NODES];
__device__ int g_bsum[SCAN_NB];
__device__ int g_boff[SCAN_NB];
__device__ int g_is64;

// ---------------- baseline-PTX helpers (no sm_103a-only features) ----------
__device__ __forceinline__ uint32_t smem_u32(const void* p) {
    uint32_t a;
    asm("{ .reg .u64 t; cvta.to.shared.u64 t, %1; cvt.u32.u64 %0, t; }"
        : "=r"(a) : "l"(p));
    return a;
}
#define LDSM4(r0, r1, r2, r3, a) \
    asm volatile("ldmatrix.sync.aligned.m8n8.x4.shared.b16 {%0,%1,%2,%3}, [%4];" \
                 : "=r"(r0), "=r"(r1), "=r"(r2), "=r"(r3) : "r"(a))
#define LDSM2(r0, r1, a) \
    asm volatile("ldmatrix.sync.aligned.m8n8.x2.shared.b16 {%0,%1}, [%2];" \
                 : "=r"(r0), "=r"(r1) : "r"(a))
#define MMA16816(c, a, b) \
    asm volatile("mma.sync.aligned.m16n8k16.row.col.f32.bf16.bf16.f32 " \
                 "{%0,%1,%2,%3}, {%4,%5,%6,%7}, {%8,%9}, {%0,%1,%2,%3};" \
                 : "+f"((c)[0]), "+f"((c)[1]), "+f"((c)[2]), "+f"((c)[3]) \
                 : "r"((a)[0]), "r"((a)[1]), "r"((a)[2]), "r"((a)[3]), \
                   "r"((b)[0]), "r"((b)[1]))

// ---------------- edge dtype detection -------------------------------------
__global__ void detect_kernel(const int* e32) {
    if (threadIdx.x == 0) {
        int is64 = 1;
        #pragma unroll
        for (int i = 0; i < 32; ++i)
            if (e32[2 * i + 1] != 0) { is64 = 0; break; }
        g_is64 = is64;
    }
}

__global__ void zerodeg_kernel() {
    int i = blockIdx.x * blockDim.x + threadIdx.x;
    if (i < N_NODES) g_degi[i] = 0;
}

__global__ void convert_kernel(const void* __restrict__ edges) {
    int i = blockIdx.x * blockDim.x + threadIdx.x;
    if (i >= 2 * NE) return;
    int v;
    if (g_is64) v = (int)((const long long*)edges)[i];
    else        v = ((const int*)edges)[i];
    g_eidx[i] = v;
    if (i >= NE) atomicAdd(&g_degi[v], 1);
}

// ---------------- hierarchical exclusive scan ------------------------------
__global__ void scan1_kernel() {
    __shared__ int wsum[8];
    int i = blockIdx.x * SCAN_BS + threadIdx.x;
    int v = (i < N_NODES) ? g_degi[i] : 0;
    #pragma unroll
    for (int off = 16; off > 0; off >>= 1) v += __shfl_down_sync(0xffffffffu, v, off);
    if ((threadIdx.x & 31) == 0) wsum[threadIdx.x >> 5] = v;
    __syncthreads();
    if (threadIdx.x < 8) {
        int s = wsum[threadIdx.x];
        #pragma unroll
        for (int off = 4; off > 0; off >>= 1) s += __shfl_down_sync(0xffu, s, off);
        if (threadIdx.x == 0) g_bsum[blockIdx.x] = s;
    }
}
__global__ void scan2_kernel() {
    __shared__ int sh[SCAN_BS];
    int t = threadIdx.x;
    int v = (t < SCAN_NB) ? g_bsum[t] : 0;
    sh[t] = v;
    __syncthreads();
    for (int off = 1; off < SCAN_BS; off <<= 1) {
        int u = (t >= off) ? sh[t - off] : 0;
        __syncthreads();
        sh[t] += u;
        __syncthreads();
    }
    if (t < SCAN_NB) g_boff[t] = sh[t] - v;
    if (t == 0) g_rowptr[N_NODES] = NE;
}
__global__ void scan3_kernel() {
    __shared__ int woff[8];
    int i = blockIdx.x * SCAN_BS + threadIdx.x;
    int lane = threadIdx.x & 31, warp = threadIdx.x >> 5;
    int v = (i < N_NODES) ? g_degi[i] : 0;
    int s = v;
    #pragma unroll
    for (int off = 1; off < 32; off <<= 1) {
        int u = __shfl_up_sync(0xffffffffu, s, off);
        if (lane >= off) s += u;
    }
    if (lane == 31) woff[warp] = s;
    __syncthreads();
    if (threadIdx.x < 8) {
        int ws = woff[threadIdx.x];
        #pragma unroll
        for (int off = 1; off < 8; off <<= 1) {
            int u = __shfl_up_sync(0xffu, ws, off);
            if ((int)threadIdx.x >= off) ws += u;
        }
        woff[threadIdx.x] = ws;
    }
    __syncthreads();
    int excl = s - v + (warp > 0 ? woff[warp - 1] : 0) + g_boff[blockIdx.x];
    if (i < N_NODES) { g_rowptr[i] = excl; g_cur[i] = excl; }
}

__global__ void fill_kernel() {
    int e = blockIdx.x * blockDim.x + threadIdx.x;
    if (e >= NE) return;
    int s = g_eidx[e];
    int d = g_eidx[NE + e];
    int pos = atomicAdd(&g_cur[d], 1);
    g_csr[pos] = s;
}

// ---------------- bf16 split prep ------------------------------------------
__global__ void split_x_kernel(const float* __restrict__ x) {
    int i = blockIdx.x * blockDim.x + threadIdx.x;    // float4 idx
    if (i >= N_NODES * F / 4) return;
    float4 v = ((const float4*)x)[i];
    __nv_bfloat162 h0 = __floats2bfloat162_rn(v.x, v.y);
    __nv_bfloat162 h1 = __floats2bfloat162_rn(v.z, v.w);
    __nv_bfloat162 l0 = __floats2bfloat162_rn(v.x - __low2float(h0), v.y - __high2float(h0));
    __nv_bfloat162 l1 = __floats2bfloat162_rn(v.z - __low2float(h1), v.w - __high2float(h1));
    ((__nv_bfloat162*)g_xhi)[i * 2]     = h0;
    ((__nv_bfloat162*)g_xhi)[i * 2 + 1] = h1;
    ((__nv_bfloat162*)g_xlo)[i * 2]     = l0;
    ((__nv_bfloat162*)g_xlo)[i * 2 + 1] = l1;
}

__global__ void split_w_kernel(const float* __restrict__ W1,
                               const float* __restrict__ W2) {
    int i = blockIdx.x * blockDim.x + threadIdx.x;
    if (i < F * F) {
        int k = i >> 7, n = i & 127;
        float v = W1[i];
        __nv_bfloat16 h = __float2bfloat16(v);
        g_b1hi[n * F + k] = h;
        g_b1lo[n * F + k] = __float2bfloat16(v - __bfloat162float(h));
    } else if (i < F * F + F * NOUT2) {
        int j = i - F * F;
        int k = j >> 5, n = j & 31;
        float v = W2[j];
        __nv_bfloat16 h = __float2bfloat16(v);
        g_b2hi[n * F + k] = h;
        g_b2lo[n * F + k] = __float2bfloat16(v - __bfloat162float(h));
    }
}

// ---------------- mma.sync GEMM: Y[64-row tiles x NCOLS] = A @ B^T ---------
// A hi/lo bf16 [N_NODES][128]; B = W^T hi/lo bf16 [NCOLS][128] (row-major n,k).
// 3 passes: hi*hi + hi*lo + lo*hi, fp32 accumulators (HMMA m16n8k16).
template<int NCOLS, int LAYER>
__global__ __launch_bounds__(256) void gemm_mma_kernel() {
    constexpr int ROWS = 64;
    constexpr int SROW = 136;                       // bf16 elements per smem row
    constexpr int A_BYTES = ROWS * SROW * 2;        // 17408
    constexpr int B_BYTES = NCOLS * SROW * 2;
    constexpr int OF_AHI = 0;
    constexpr int OF_ALO = A_BYTES;
    constexpr int OF_BHI = 2 * A_BYTES;
    constexpr int OF_BLO = OF_BHI + B_BYTES;
    constexpr int N8  = NCOLS / 32;                 // n8 tiles per warp (4 or 1)
    constexpr int WNT = NCOLS / 4;                  // warp n-tile (32 or 8)
    constexpr int CS  = NCOLS + 4;                  // Csm fp32 stride

    const __nv_bfloat16* Ahi = (LAYER == 1) ? g_xhi  : g_h1hi;
    const __nv_bfloat16* Alo = (LAYER == 1) ? g_xlo  : g_h1lo;
    const __nv_bfloat16* Bhi = (LAYER == 1) ? g_b1hi : g_b2hi;
    const __nv_bfloat16* Blo = (LAYER == 1) ? g_b1lo : g_b2lo;
    float* Y = (LAYER == 1) ? g_y1 : g_y2;

    extern __shared__ char smem[];
    float* Csm = (float*)smem;          // overlays A region after compute
    uint32_t sb = smem_u32(smem);

    int t = threadIdx.x, lane = t & 31, wid = t >> 5;
    int row0 = blockIdx.x * ROWS;

    // stage A hi/lo (zero-fill past N_NODES)
    for (int i = t; i < ROWS * 16; i += 256) {
        int r = i >> 4, c = (i & 15) * 8;
        int gr = row0 + r;
        uint4 vh = make_uint4(0, 0, 0, 0), vl = make_uint4(0, 0, 0, 0);
        if (gr < N_NODES) {
            vh = *(const uint4*)(Ahi + (size_t)gr * F + c);
            vl = *(const uint4*)(Alo + (size_t)gr * F + c);
        }
        *(uint4*)(smem + OF_AHI + r * (SROW * 2) + c * 2) = vh;
        *(uint4*)(smem + OF_ALO + r * (SROW * 2) + c * 2) = vl;
    }
    // stage B hi/lo
    for (int i = t; i < NCOLS * 16; i += 256) {
        int r = i >> 4, c = (i & 15) * 8;
        *(uint4*)(smem + OF_BHI + r * (SROW * 2) + c * 2) =
            *(const uint4*)(Bhi + (size_t)r * F + c);
        *(uint4*)(smem + OF_BLO + r * (SROW * 2) + c * 2) =
            *(const uint4*)(Blo + (size_t)r * F + c);
    }
    __syncthreads();

    int wm = wid & 1, wn = wid >> 1;      // 2 m-warps x 4 n-warps
    int m0 = wm * 32, n0 = wn * WNT;

    float acc[2][N8][4];
    #pragma unroll
    for (int mi = 0; mi < 2; ++mi)
        #pragma unroll
        for (int nj = 0; nj < N8; ++nj)
            #pragma unroll
            for (int q = 0; q < 4; ++q) acc[mi][nj][q] = 0.f;

    int lrow = lane & 7, lsub = lane >> 3;
    int aRow = lrow + (lsub & 1) * 8, aCol = (lsub >> 1) * 8;
    int bRow = lrow + (lsub >> 1) * 8, bCol = (lsub & 1) * 8;
    int l16 = lane & 15;
    int b2Row = l16 & 7, b2Col = (l16 >> 3) * 8;

    const int passA[3] = { OF_AHI, OF_AHI, OF_ALO };
    const int passB[3] = { OF_BHI, OF_BLO, OF_BHI };

    #pragma unroll
    for (int p = 0; p < 3; ++p) {
        uint32_t Ab = sb + passA[p], Bb = sb + passB[p];
        #pragma unroll
        for (int k = 0; k < 8; ++k) {
            int k0 = k * 16;
            uint32_t a[2][4];
            #pragma unroll
            for (int mi = 0; mi < 2; ++mi) {
                uint32_t ad = Ab + ((m0 + mi * 16 + aRow) * SROW + k0 + aCol) * 2;
                LDSM4(a[mi][0], a[mi][1], a[mi][2], a[mi][3], ad);
            }
            uint32_t b[N8][2];
            if constexpr (N8 == 1) {
                uint32_t bd = Bb + ((n0 + b2Row) * SROW + k0 + b2Col) * 2;
                LDSM2(b[0][0], b[0][1], bd);
            } else {
                #pragma unroll
                for (int nj2 = 0; nj2 < N8 / 2; ++nj2) {
                    uint32_t bd = Bb + ((n0 + nj2 * 16 + bRow) * SROW + k0 + bCol) * 2;
                    uint32_t r0, r1, r2, r3;
                    LDSM4(r0, r1, r2, r3, bd);
                    b[nj2 * 2][0] = r0; b[nj2 * 2][1] = r1;
                    b[nj2 * 2 + 1][0] = r2; b[nj2 * 2 + 1][1] = r3;
                }
            }
            #pragma unroll
            for (int mi = 0; mi < 2; ++mi)
                #pragma unroll
                for (int nj = 0; nj < N8; ++nj)
                    MMA16816(acc[mi][nj], a[mi], b[nj]);
        }
    }

    __syncthreads();    // everyone done reading A/B smem

    // C fragments -> Csm (fp32, coalesced-store staging)
    int g = lane >> 2, tp = lane & 3;
    #pragma unroll
    for (int mi = 0; mi < 2; ++mi)
        #pragma unroll
        for (int nj = 0; nj < N8; ++nj) {
            int rr = m0 + mi * 16 + g;
            int cc = n0 + nj * 8 + tp * 2;
            Csm[rr * CS + cc]           = acc[mi][nj][0];
            Csm[rr * CS + cc + 1]       = acc[mi][nj][1];
            Csm[(rr + 8) * CS + cc]     = acc[mi][nj][2];
            Csm[(rr + 8) * CS + cc + 1] = acc[mi][nj][3];
        }
    __syncthreads();

    for (int i = t; i < ROWS * (NCOLS / 4); i += 256) {
        int r = i / (NCOLS / 4), c4 = i % (NCOLS / 4);
        int row = row0 + r;
        if (row < N_NODES)
            ((float4*)(Y + (size_t)row * NCOLS))[c4] = *(float4*)&Csm[r * CS + c4 * 4];
    }
}

// ---------------- agg1: h1 = leaky((sum_nbr y1 + y1) * rinv + b1) -> bf16 --
__global__ void agg1_kernel(const float* __restrict__ b1g) {
    int w = (blockIdx.x * blockDim.x + threadIdx.x) >> 5;
    if (w >= N_NODES) return;
    int lane = threadIdx.x & 31;
    const float4* Y = (const float4*)g_y1;

    float4 a0 = Y[(size_t)w * 32 + lane];
    float4 a1 = make_float4(0.f, 0.f, 0.f, 0.f);
    int beg = g_rowptr[w], end = g_rowptr[w + 1];
    int j = beg;
    for (; j + 2 <= end; j += 2) {
        int s0 = g_csr[j], s1 = g_csr[j + 1];
        float4 v0 = Y[(size_t)s0 * 32 + lane];
        float4 v1 = Y[(size_t)s1 * 32 + lane];
        a0.x += v0.x; a0.y += v0.y; a0.z += v0.z; a0.w += v0.w;
        a1.x += v1.x; a1.y += v1.y; a1.z += v1.z; a1.w += v1.w;
    }
    if (j < end) {
        int s = g_csr[j];
        float4 v = Y[(size_t)s * 32 + lane];
        a0.x += v.x; a0.y += v.y; a0.z += v.z; a0.w += v.w;
    }

    float rinv = 1.0f / (float)(end - beg + 1);
    float4 b = ((const float4*)b1g)[lane];
    float4 h;
    h.x = (a0.x + a1.x) * rinv + b.x;
    h.y = (a0.y + a1.y) * rinv + b.y;
    h.z = (a0.z + a1.z) * rinv + b.z;
    h.w = (a0.w + a1.w) * rinv + b.w;
    h.x = h.x >= 0.f ? h.x : 0.01f * h.x;
    h.y = h.y >= 0.f ? h.y : 0.01f * h.y;
    h.z = h.z >= 0.f ? h.z : 0.01f * h.z;
    h.w = h.w >= 0.f ? h.w : 0.01f * h.w;

    __nv_bfloat162 p0 = __floats2bfloat162_rn(h.x, h.y);
    __nv_bfloat162 p1 = __floats2bfloat162_rn(h.z, h.w);
    __nv_bfloat162 q0 = __floats2bfloat162_rn(h.x - __low2float(p0), h.y - __high2float(p0));
    __nv_bfloat162 q1 = __floats2bfloat162_rn(h.z - __low2float(p1), h.w - __high2float(p1));
    ((__nv_bfloat162*)g_h1hi)[(size_t)w * 64 + lane * 2]     = p0;
    ((__nv_bfloat162*)g_h1hi)[(size_t)w * 64 + lane * 2 + 1] = p1;
    ((__nv_bfloat162*)g_h1lo)[(size_t)w * 64 + lane * 2]     = q0;
    ((__nv_bfloat162*)g_h1lo)[(size_t)w * 64 + lane * 2 + 1] = q1;
}

// ---------------- agg2: out = (sum_nbr y2 + y2) * rinv + b2 ----------------
__global__ void agg2_kernel(const float* __restrict__ b2g,
                            float* __restrict__ out) {
    int gw = (blockIdx.x * blockDim.x + threadIdx.x) >> 5;
    int lane = threadIdx.x & 31;
    int node = gw * 4 + (lane >> 3);
    if (node >= N_NODES) return;
    int l8 = lane & 7;
    const float4* Y = (const float4*)g_y2;

    float4 a0 = Y[(size_t)node * 8 + l8];
    float4 a1 = make_float4(0.f, 0.f, 0.f, 0.f);
    int beg = g_rowptr[node], end = g_rowptr[node + 1];
    int j = beg;
    for (; j + 2 <= end; j += 2) {
        int s0 = g_csr[j], s1 = g_csr[j + 1];
        float4 v0 = Y[(size_t)s0 * 8 + l8];
        float4 v1 = Y[(size_t)s1 * 8 + l8];
        a0.x += v0.x; a0.y += v0.y; a0.z += v0.z; a0.w += v0.w;
        a1.x += v1.x; a1.y += v1.y; a1.z += v1.z; a1.w += v1.w;
    }
    if (j < end) {
        int s = g_csr[j];
        float4 v = Y[(size_t)s * 8 + l8];
        a0.x += v.x; a0.y += v.y; a0.z += v.z; a0.w += v.w;
    }

    float rinv = 1.0f / (float)(end - beg + 1);
    float4 b = ((const float4*)b2g)[l8];
    float4 o;
    o.x = (a0.x + a1.x) * rinv + b.x;
    o.y = (a0.y + a1.y) * rinv + b.y;
    o.z = (a0.z + a1.z) * rinv + b.z;
    o.w = (a0.w + a1.w) * rinv + b.w;
    ((float4*)(out + (size_t)node * NOUT2))[l8] = o;
}

// ---------------- launch ----------------------------------------------------
extern "C" void kernel_launch(void* const* d_in, const int* in_sizes, int n_in,
                              void* d_out, int out_size) {
    const float* in_feat = (const float*)d_in[0];
    const void*  edges   = d_in[1];
    const float* W1      = (const float*)d_in[2];
    const float* b1      = (const float*)d_in[3];
    const float* W2      = (const float*)d_in[4];
    const float* b2      = (const float*)d_in[5];
    float* out = (float*)d_out;

    const int smem_g1 = 2 * (64 * 136 * 2) + 2 * (128 * 136 * 2);   // 104,448
    const int smem_g2 = 2 * (64 * 136 * 2) + 2 * (32 * 136 * 2);    //  52,224
    cudaFuncSetAttribute(gemm_mma_kernel<128, 1>,
                         cudaFuncAttributeMaxDynamicSharedMemorySize, smem_g1);
    cudaFuncSetAttribute(gemm_mma_kernel<32, 2>,
                         cudaFuncAttributeMaxDynamicSharedMemorySize, smem_g2);

    detect_kernel<<<1, 32>>>((const int*)edges);
    zerodeg_kernel<<<(N_NODES + 255) / 256, 256>>>();
    convert_kernel<<<(2 * NE + 255) / 256, 256>>>(edges);
    scan1_kernel<<<SCAN_NB, SCAN_BS>>>();
    scan2_kernel<<<1, SCAN_BS>>>();
    scan3_kernel<<<SCAN_NB, SCAN_BS>>>();
    fill_kernel<<<(NE + 255) / 256, 256>>>();

    split_x_kernel<<<(N_NODES * F / 4 + 255) / 256, 256>>>(in_feat);
    split_w_kernel<<<(F * F + F * NOUT2 + 255) / 256, 256>>>(W1, W2);

    const int GB = (N_NODES + 63) / 64;   // 782
    gemm_mma_kernel<128, 1><<<GB, 256, smem_g1>>>();
    agg1_kernel<<<(N_NODES * 32 + 255) / 256, 256>>>(b1);
    gemm_mma_kernel<32, 2><<<GB, 256, smem_g2>>>();
    agg2_kernel<<<((N_NODES + 3) / 4 * 32 + 255) / 256, 256>>>(b2, out);
}

// round 7
// speedup vs baseline: 1.7943x; 1.0755x over previous
#include <cuda_runtime.h>
#include <cuda_bf16.h>
#include <cuda_fp16.h>
#include <cstdint>

#define N_NODES 50000
#define F 128
#define NOUT2 32
#define NE 800000

#define SCAN_BS 256
#define SCAN_NB ((N_NODES + SCAN_BS - 1) / SCAN_BS)   // 196

// ---------------- scratch (device globals: no allocation allowed) ----------
__device__ __align__(16) __half g_y1h[N_NODES * F];      // x @ W1 (fp16)
__device__ __align__(16) __half g_y2h[N_NODES * NOUT2];  // h1 @ W2 (fp16)
__device__ __align__(16) __nv_bfloat16 g_xhi[N_NODES * F];
__device__ __align__(16) __nv_bfloat16 g_xlo[N_NODES * F];
__device__ __align__(16) __nv_bfloat16 g_h1hi[N_NODES * F];
__device__ __align__(16) __nv_bfloat16 g_h1lo[N_NODES * F];
__device__ __align__(16) __nv_bfloat16 g_b1hi[F * F];     // W1^T [n][k]
__device__ __align__(16) __nv_bfloat16 g_b1lo[F * F];
__device__ __align__(16) __nv_bfloat16 g_b2hi[NOUT2 * F]; // W2^T [n][k]
__device__ __align__(16) __nv_bfloat16 g_b2lo[NOUT2 * F];
__device__ int g_csr[NE];
__device__ int g_rowptr[N_NODES + 1];
__device__ int g_cur[N_NODES];
__device__ int g_degi[N_NODES];
__device__ int g_bsum[SCAN_NB];
__device__ int g_boff[SCAN_NB];
__device__ int g_is64;

// ---------------- helpers ---------------------------------------------------
__device__ __forceinline__ uint32_t smem_u32(const void* p) {
    uint32_t a;
    asm("{ .reg .u64 t; cvta.to.shared.u64 t, %1; cvt.u32.u64 %0, t; }"
        : "=r"(a) : "l"(p));
    return a;
}
#define LDSM4(r0, r1, r2, r3, a) \
    asm volatile("ldmatrix.sync.aligned.m8n8.x4.shared.b16 {%0,%1,%2,%3}, [%4];" \
                 : "=r"(r0), "=r"(r1), "=r"(r2), "=r"(r3) : "r"(a))
#define LDSM2(r0, r1, a) \
    asm volatile("ldmatrix.sync.aligned.m8n8.x2.shared.b16 {%0,%1}, [%2];" \
                 : "=r"(r0), "=r"(r1) : "r"(a))
#define MMA16816(c, a, b) \
    asm volatile("mma.sync.aligned.m16n8k16.row.col.f32.bf16.bf16.f32 " \
                 "{%0,%1,%2,%3}, {%4,%5,%6,%7}, {%8,%9}, {%0,%1,%2,%3};" \
                 : "+f"((c)[0]), "+f"((c)[1]), "+f"((c)[2]), "+f"((c)[3]) \
                 : "r"((a)[0]), "r"((a)[1]), "r"((a)[2]), "r"((a)[3]), \
                   "r"((b)[0]), "r"((b)[1]))

// uint2 holding 4 consecutive halves -> float4, accumulate
__device__ __forceinline__ void acc_h4(float4& a, uint2 u) {
    float2 f0 = __half22float2(*reinterpret_cast<__half2*>(&u.x));
    float2 f1 = __half22float2(*reinterpret_cast<__half2*>(&u.y));
    a.x += f0.x; a.y += f0.y; a.z += f1.x; a.w += f1.y;
}

// ---------------- init: zero degrees + edge dtype detection ----------------
__global__ void init_kernel(const int* e32) {
    int i = blockIdx.x * blockDim.x + threadIdx.x;
    if (i < N_NODES) g_degi[i] = 0;
    if (i == 0) {
        int is64 = 1;
        #pragma unroll
        for (int k = 0; k < 32; ++k)
            if (e32[2 * k + 1] != 0) { is64 = 0; break; }
        g_is64 = is64;
    }
}

// ---------------- degree histogram -----------------------------------------
__global__ void deg_kernel(const void* __restrict__ edges) {
    int e = blockIdx.x * blockDim.x + threadIdx.x;
    if (e >= NE) return;
    int d;
    if (g_is64) d = (int)((const long long*)edges)[NE + e];
    else        d = ((const int*)edges)[NE + e];
    atomicAdd(&g_degi[d], 1);
}

// ---------------- hierarchical exclusive scan ------------------------------
__global__ void scan1_kernel() {
    __shared__ int wsum[8];
    int i = blockIdx.x * SCAN_BS + threadIdx.x;
    int v = (i < N_NODES) ? g_degi[i] : 0;
    #pragma unroll
    for (int off = 16; off > 0; off >>= 1) v += __shfl_down_sync(0xffffffffu, v, off);
    if ((threadIdx.x & 31) == 0) wsum[threadIdx.x >> 5] = v;
    __syncthreads();
    if (threadIdx.x < 8) {
        int s = wsum[threadIdx.x];
        #pragma unroll
        for (int off = 4; off > 0; off >>= 1) s += __shfl_down_sync(0xffu, s, off);
        if (threadIdx.x == 0) g_bsum[blockIdx.x] = s;
    }
}
__global__ void scan2_kernel() {
    __shared__ int sh[SCAN_BS];
    int t = threadIdx.x;
    int v = (t < SCAN_NB) ? g_bsum[t] : 0;
    sh[t] = v;
    __syncthreads();
    for (int off = 1; off < SCAN_BS; off <<= 1) {
        int u = (t >= off) ? sh[t - off] : 0;
        __syncthreads();
        sh[t] += u;
        __syncthreads();
    }
    if (t < SCAN_NB) g_boff[t] = sh[t] - v;
    if (t == 0) g_rowptr[N_NODES] = NE;
}
__global__ void scan3_kernel() {
    __shared__ int woff[8];
    int i = blockIdx.x * SCAN_BS + threadIdx.x;
    int lane = threadIdx.x & 31, warp = threadIdx.x >> 5;
    int v = (i < N_NODES) ? g_degi[i] : 0;
    int s = v;
    #pragma unroll
    for (int off = 1; off < 32; off <<= 1) {
        int u = __shfl_up_sync(0xffffffffu, s, off);
        if (lane >= off) s += u;
    }
    if (lane == 31) woff[warp] = s;
    __syncthreads();
    if (threadIdx.x < 8) {
        int ws = woff[threadIdx.x];
        #pragma unroll
        for (int off = 1; off < 8; off <<= 1) {
            int u = __shfl_up_sync(0xffu, ws, off);
            if ((int)threadIdx.x >= off) ws += u;
        }
        woff[threadIdx.x] = ws;
    }
    __syncthreads();
    int excl = s - v + (warp > 0 ? woff[warp - 1] : 0) + g_boff[blockIdx.x];
    if (i < N_NODES) { g_rowptr[i] = excl; g_cur[i] = excl; }
}

// ---------------- CSR fill (reads edges directly) --------------------------
__global__ void fill_kernel(const void* __restrict__ edges) {
    int e = blockIdx.x * blockDim.x + threadIdx.x;
    if (e >= NE) return;
    int s, d;
    if (g_is64) {
        s = (int)((const long long*)edges)[e];
        d = (int)((const long long*)edges)[NE + e];
    } else {
        s = ((const int*)edges)[e];
        d = ((const int*)edges)[NE + e];
    }
    int pos = atomicAdd(&g_cur[d], 1);
    g_csr[pos] = s;
}

// ---------------- bf16 split prep (x + W1 + W2 in one kernel) --------------
#define NX4 (N_NODES * F / 4)
__global__ void split_kernel(const float* __restrict__ x,
                             const float* __restrict__ W1,
                             const float* __restrict__ W2) {
    int i = blockIdx.x * blockDim.x + threadIdx.x;
    if (i < NX4) {
        float4 v = ((const float4*)x)[i];
        __nv_bfloat162 h0 = __floats2bfloat162_rn(v.x, v.y);
        __nv_bfloat162 h1 = __floats2bfloat162_rn(v.z, v.w);
        __nv_bfloat162 l0 = __floats2bfloat162_rn(v.x - __low2float(h0), v.y - __high2float(h0));
        __nv_bfloat162 l1 = __floats2bfloat162_rn(v.z - __low2float(h1), v.w - __high2float(h1));
        ((__nv_bfloat162*)g_xhi)[i * 2]     = h0;
        ((__nv_bfloat162*)g_xhi)[i * 2 + 1] = h1;
        ((__nv_bfloat162*)g_xlo)[i * 2]     = l0;
        ((__nv_bfloat162*)g_xlo)[i * 2 + 1] = l1;
    } else {
        int j = i - NX4;
        if (j < F * F) {
            int k = j >> 7, n = j & 127;
            float v = W1[j];
            __nv_bfloat16 h = __float2bfloat16(v);
            g_b1hi[n * F + k] = h;
            g_b1lo[n * F + k] = __float2bfloat16(v - __bfloat162float(h));
        } else if (j < F * F + F * NOUT2) {
            int q = j - F * F;
            int k = q >> 5, n = q & 31;
            float v = W2[q];
            __nv_bfloat16 h = __float2bfloat16(v);
            g_b2hi[n * F + k] = h;
            g_b2lo[n * F + k] = __float2bfloat16(v - __bfloat162float(h));
        }
    }
}

// ---------------- mma.sync GEMM: Yh[64-row tiles x NCOLS] = A @ B^T (fp16) -
template<int NCOLS, int LAYER>
__global__ __launch_bounds__(256) void gemm_mma_kernel() {
    constexpr int ROWS = 64;
    constexpr int SROW = 136;
    constexpr int A_BYTES = ROWS * SROW * 2;
    constexpr int B_BYTES = NCOLS * SROW * 2;
    constexpr int OF_AHI = 0;
    constexpr int OF_ALO = A_BYTES;
    constexpr int OF_BHI = 2 * A_BYTES;
    constexpr int OF_BLO = OF_BHI + B_BYTES;
    constexpr int N8  = NCOLS / 32;
    constexpr int WNT = NCOLS / 4;
    constexpr int CS  = NCOLS + 4;

    const __nv_bfloat16* Ahi = (LAYER == 1) ? g_xhi  : g_h1hi;
    const __nv_bfloat16* Alo = (LAYER == 1) ? g_xlo  : g_h1lo;
    const __nv_bfloat16* Bhi = (LAYER == 1) ? g_b1hi : g_b2hi;
    const __nv_bfloat16* Blo = (LAYER == 1) ? g_b1lo : g_b2lo;
    __half* Yh = (LAYER == 1) ? g_y1h : g_y2h;

    extern __shared__ char smem[];
    float* Csm = (float*)smem;
    uint32_t sb = smem_u32(smem);

    int t = threadIdx.x, lane = t & 31, wid = t >> 5;
    int row0 = blockIdx.x * ROWS;

    for (int i = t; i < ROWS * 16; i += 256) {
        int r = i >> 4, c = (i & 15) * 8;
        int gr = row0 + r;
        uint4 vh = make_uint4(0, 0, 0, 0), vl = make_uint4(0, 0, 0, 0);
        if (gr < N_NODES) {
            vh = *(const uint4*)(Ahi + (size_t)gr * F + c);
            vl = *(const uint4*)(Alo + (size_t)gr * F + c);
        }
        *(uint4*)(smem + OF_AHI + r * (SROW * 2) + c * 2) = vh;
        *(uint4*)(smem + OF_ALO + r * (SROW * 2) + c * 2) = vl;
    }
    for (int i = t; i < NCOLS * 16; i += 256) {
        int r = i >> 4, c = (i & 15) * 8;
        *(uint4*)(smem + OF_BHI + r * (SROW * 2) + c * 2) =
            *(const uint4*)(Bhi + (size_t)r * F + c);
        *(uint4*)(smem + OF_BLO + r * (SROW * 2) + c * 2) =
            *(const uint4*)(Blo + (size_t)r * F + c);
    }
    __syncthreads();

    int wm = wid & 1, wn = wid >> 1;
    int m0 = wm * 32, n0 = wn * WNT;

    float acc[2][N8][4];
    #pragma unroll
    for (int mi = 0; mi < 2; ++mi)
        #pragma unroll
        for (int nj = 0; nj < N8; ++nj)
            #pragma unroll
            for (int q = 0; q < 4; ++q) acc[mi][nj][q] = 0.f;

    int lrow = lane & 7, lsub = lane >> 3;
    int aRow = lrow + (lsub & 1) * 8, aCol = (lsub >> 1) * 8;
    int bRow = lrow + (lsub >> 1) * 8, bCol = (lsub & 1) * 8;
    int l16 = lane & 15;
    int b2Row = l16 & 7, b2Col = (l16 >> 3) * 8;

    const int passA[3] = { OF_AHI, OF_AHI, OF_ALO };
    const int passB[3] = { OF_BHI, OF_BLO, OF_BHI };

    #pragma unroll
    for (int p = 0; p < 3; ++p) {
        uint32_t Ab = sb + passA[p], Bb = sb + passB[p];
        #pragma unroll
        for (int k = 0; k < 8; ++k) {
            int k0 = k * 16;
            uint32_t a[2][4];
            #pragma unroll
            for (int mi = 0; mi < 2; ++mi) {
                uint32_t ad = Ab + ((m0 + mi * 16 + aRow) * SROW + k0 + aCol) * 2;
                LDSM4(a[mi][0], a[mi][1], a[mi][2], a[mi][3], ad);
            }
            uint32_t b[N8][2];
            if constexpr (N8 == 1) {
                uint32_t bd = Bb + ((n0 + b2Row) * SROW + k0 + b2Col) * 2;
                LDSM2(b[0][0], b[0][1], bd);
            } else {
                #pragma unroll
                for (int nj2 = 0; nj2 < N8 / 2; ++nj2) {
                    uint32_t bd = Bb + ((n0 + nj2 * 16 + bRow) * SROW + k0 + bCol) * 2;
                    uint32_t r0, r1, r2, r3;
                    LDSM4(r0, r1, r2, r3, bd);
                    b[nj2 * 2][0] = r0; b[nj2 * 2][1] = r1;
                    b[nj2 * 2 + 1][0] = r2; b[nj2 * 2 + 1][1] = r3;
                }
            }
            #pragma unroll
            for (int mi = 0; mi < 2; ++mi)
                #pragma unroll
                for (int nj = 0; nj < N8; ++nj)
                    MMA16816(acc[mi][nj], a[mi], b[nj]);
        }
    }

    __syncthreads();

    int g = lane >> 2, tp = lane & 3;
    #pragma unroll
    for (int mi = 0; mi < 2; ++mi)
        #pragma unroll
        for (int nj = 0; nj < N8; ++nj) {
            int rr = m0 + mi * 16 + g;
            int cc = n0 + nj * 8 + tp * 2;
            Csm[rr * CS + cc]           = acc[mi][nj][0];
            Csm[rr * CS + cc + 1]       = acc[mi][nj][1];
            Csm[(rr + 8) * CS + cc]     = acc[mi][nj][2];
            Csm[(rr + 8) * CS + cc + 1] = acc[mi][nj][3];
        }
    __syncthreads();

    // store as fp16: 8 halves (16B) per thread iteration
    for (int i = t; i < ROWS * (NCOLS / 8); i += 256) {
        int r = i / (NCOLS / 8), c8 = (i % (NCOLS / 8)) * 8;
        int row = row0 + r;
        if (row < N_NODES) {
            float4 u = *(float4*)&Csm[r * CS + c8];
            float4 w = *(float4*)&Csm[r * CS + c8 + 4];
            __half2 p0 = __floats2half2_rn(u.x, u.y);
            __half2 p1 = __floats2half2_rn(u.z, u.w);
            __half2 p2 = __floats2half2_rn(w.x, w.y);
            __half2 p3 = __floats2half2_rn(w.z, w.w);
            uint4 o;
            o.x = *reinterpret_cast<uint32_t*>(&p0);
            o.y = *reinterpret_cast<uint32_t*>(&p1);
            o.z = *reinterpret_cast<uint32_t*>(&p2);
            o.w = *reinterpret_cast<uint32_t*>(&p3);
            *(uint4*)(Yh + (size_t)row * NCOLS + c8) = o;
        }
    }
}

// ---------------- agg1: h1 = leaky((sum_nbr y1 + y1)*rinv + b1) -> bf16 ----
// warp per node; lane covers 4 halves (uint2). 4-way MLP unroll.
__global__ void agg1_kernel(const float* __restrict__ b1g) {
    int w = (blockIdx.x * blockDim.x + threadIdx.x) >> 5;
    if (w >= N_NODES) return;
    int lane = threadIdx.x & 31;
    const uint2* Y = (const uint2*)g_y1h;   // row = 32 uint2

    float4 a0 = make_float4(0.f, 0.f, 0.f, 0.f);
    float4 a1 = a0, a2 = a0, a3 = a0;
    acc_h4(a0, Y[(size_t)w * 32 + lane]);   // self

    int beg = g_rowptr[w], end = g_rowptr[w + 1];
    int j = beg;
    for (; j + 4 <= end; j += 4) {
        int s0 = g_csr[j], s1 = g_csr[j + 1], s2 = g_csr[j + 2], s3 = g_csr[j + 3];
        acc_h4(a0, Y[(size_t)s0 * 32 + lane]);
        acc_h4(a1, Y[(size_t)s1 * 32 + lane]);
        acc_h4(a2, Y[(size_t)s2 * 32 + lane]);
        acc_h4(a3, Y[(size_t)s3 * 32 + lane]);
    }
    for (; j < end; ++j)
        acc_h4(a0, Y[(size_t)g_csr[j] * 32 + lane]);

    float rinv = 1.0f / (float)(end - beg + 1);
    float4 b = ((const float4*)b1g)[lane];
    float4 h;
    h.x = (a0.x + a1.x + a2.x + a3.x) * rinv + b.x;
    h.y = (a0.y + a1.y + a2.y + a3.y) * rinv + b.y;
    h.z = (a0.z + a1.z + a2.z + a3.z) * rinv + b.z;
    h.w = (a0.w + a1.w + a2.w + a3.w) * rinv + b.w;
    h.x = h.x >= 0.f ? h.x : 0.01f * h.x;
    h.y = h.y >= 0.f ? h.y : 0.01f * h.y;
    h.z = h.z >= 0.f ? h.z : 0.01f * h.z;
    h.w = h.w >= 0.f ? h.w : 0.01f * h.w;

    __nv_bfloat162 p0 = __floats2bfloat162_rn(h.x, h.y);
    __nv_bfloat162 p1 = __floats2bfloat162_rn(h.z, h.w);
    __nv_bfloat162 q0 = __floats2bfloat162_rn(h.x - __low2float(p0), h.y - __high2float(p0));
    __nv_bfloat162 q1 = __floats2bfloat162_rn(h.z - __low2float(p1), h.w - __high2float(p1));
    ((__nv_bfloat162*)g_h1hi)[(size_t)w * 64 + lane * 2]     = p0;
    ((__nv_bfloat162*)g_h1hi)[(size_t)w * 64 + lane * 2 + 1] = p1;
    ((__nv_bfloat162*)g_h1lo)[(size_t)w * 64 + lane * 2]     = q0;
    ((__nv_bfloat162*)g_h1lo)[(size_t)w * 64 + lane * 2 + 1] = q1;
}

// ---------------- agg2: out = (sum_nbr y2 + y2)*rinv + b2 ------------------
// 8 lanes per node (4 nodes/warp); l8 covers 4 halves.
__global__ void agg2_kernel(const float* __restrict__ b2g,
                            float* __restrict__ out) {
    int gw = (blockIdx.x * blockDim.x + threadIdx.x) >> 5;
    int lane = threadIdx.x & 31;
    int node = gw * 4 + (lane >> 3);
    if (node >= N_NODES) return;
    int l8 = lane & 7;
    const uint2* Y = (const uint2*)g_y2h;   // row = 8 uint2

    float4 a0 = make_float4(0.f, 0.f, 0.f, 0.f);
    float4 a1 = a0, a2 = a0, a3 = a0;
    acc_h4(a0, Y[(size_t)node * 8 + l8]);   // self

    int beg = g_rowptr[node], end = g_rowptr[node + 1];
    int j = beg;
    for (; j + 4 <= end; j += 4) {
        int s0 = g_csr[j], s1 = g_csr[j + 1], s2 = g_csr[j + 2], s3 = g_csr[j + 3];
        acc_h4(a0, Y[(size_t)s0 * 8 + l8]);
        acc_h4(a1, Y[(size_t)s1 * 8 + l8]);
        acc_h4(a2, Y[(size_t)s2 * 8 + l8]);
        acc_h4(a3, Y[(size_t)s3 * 8 + l8]);
    }
    for (; j < end; ++j)
        acc_h4(a0, Y[(size_t)g_csr[j] * 8 + l8]);

    float rinv = 1.0f / (float)(end - beg + 1);
    float4 b = ((const float4*)b2g)[l8];
    float4 o;
    o.x = (a0.x + a1.x + a2.x + a3.x) * rinv + b.x;
    o.y = (a0.y + a1.y + a2.y + a3.y) * rinv + b.y;
    o.z = (a0.z + a1.z + a2.z + a3.z) * rinv + b.z;
    o.w = (a0.w + a1.w + a2.w + a3.w) * rinv + b.w;
    ((float4*)(out + (size_t)node * NOUT2))[l8] = o;
}

// ---------------- launch ----------------------------------------------------
extern "C" void kernel_launch(void* const* d_in, const int* in_sizes, int n_in,
                              void* d_out, int out_size) {
    const float* in_feat = (const float*)d_in[0];
    const void*  edges   = d_in[1];
    const float* W1      = (const float*)d_in[2];
    const float* b1      = (const float*)d_in[3];
    const float* W2      = (const float*)d_in[4];
    const float* b2      = (const float*)d_in[5];
    float* out = (float*)d_out;

    const int smem_g1 = 2 * (64 * 136 * 2) + 2 * (128 * 136 * 2);   // 104,448
    const int smem_g2 = 2 * (64 * 136 * 2) + 2 * (32 * 136 * 2);    //  52,224
    cudaFuncSetAttribute(gemm_mma_kernel<128, 1>,
                         cudaFuncAttributeMaxDynamicSharedMemorySize, smem_g1);
    cudaFuncSetAttribute(gemm_mma_kernel<32, 2>,
                         cudaFuncAttributeMaxDynamicSharedMemorySize, smem_g2);

    init_kernel<<<(N_NODES + 255) / 256, 256>>>((const int*)edges);
    deg_kernel<<<(NE + 255) / 256, 256>>>(edges);
    scan1_kernel<<<SCAN_NB, SCAN_BS>>>();
    scan2_kernel<<<1, SCAN_BS>>>();
    scan3_kernel<<<SCAN_NB, SCAN_BS>>>();
    fill_kernel<<<(NE + 255) / 256, 256>>>(edges);

    split_kernel<<<(NX4 + F * F + F * NOUT2 + 255) / 256, 256>>>(in_feat, W1, W2);

    const int GB = (N_NODES + 63) / 64;   // 782
    gemm_mma_kernel<128, 1><<<GB, 256, smem_g1>>>();
    agg1_kernel<<<(N_NODES * 32 + 255) / 256, 256>>>(b1);
    gemm_mma_kernel<32, 2><<<GB, 256, smem_g2>>>();
    agg2_kernel<<<((N_NODES + 3) / 4 * 32 + 255) / 256, 256>>>(b2, out);
}

// round 8
// speedup vs baseline: 1.8791x; 1.0473x over previous
#include <cuda_runtime.h>
#include <cuda_bf16.h>
#include <cuda_fp16.h>
#include <cstdint>

#define N_NODES 50000
#define F 128
#define NOUT2 32
#define NE 800000

#define SCAN_BS 256
#define SCAN_NB ((N_NODES + SCAN_BS - 1) / SCAN_BS)   // 196
#define LBFLAG 0x80000000u

// ---------------- scratch (device globals: no allocation allowed) ----------
__device__ __align__(16) __half g_y1h[N_NODES * F];      // x @ W1 (fp16)
__device__ __align__(16) __half g_y2h[N_NODES * NOUT2];  // h1 @ W2 (fp16)
__device__ __align__(16) __nv_bfloat16 g_h1hi[N_NODES * F];
__device__ __align__(16) __nv_bfloat16 g_h1lo[N_NODES * F];
__device__ __align__(16) __nv_bfloat16 g_b1hi[F * F];     // W1^T [n][k]
__device__ __align__(16) __nv_bfloat16 g_b1lo[F * F];
__device__ __align__(16) __nv_bfloat16 g_b2hi[NOUT2 * F]; // W2^T [n][k]
__device__ __align__(16) __nv_bfloat16 g_b2lo[NOUT2 * F];
__device__ int g_csr[NE];
__device__ int g_rowptr[N_NODES + 1];
__device__ int g_cur[N_NODES];
__device__ int g_degi[N_NODES];
__device__ unsigned g_lb[SCAN_NB];     // lookback aggregates (flag-packed)
__device__ int g_is64;

// ---------------- helpers ---------------------------------------------------
__device__ __forceinline__ uint32_t smem_u32(const void* p) {
    uint32_t a;
    asm("{ .reg .u64 t; cvta.to.shared.u64 t, %1; cvt.u32.u64 %0, t; }"
        : "=r"(a) : "l"(p));
    return a;
}
#define LDSM4(r0, r1, r2, r3, a) \
    asm volatile("ldmatrix.sync.aligned.m8n8.x4.shared.b16 {%0,%1,%2,%3}, [%4];" \
                 : "=r"(r0), "=r"(r1), "=r"(r2), "=r"(r3) : "r"(a))
#define LDSM2(r0, r1, a) \
    asm volatile("ldmatrix.sync.aligned.m8n8.x2.shared.b16 {%0,%1}, [%2];" \
                 : "=r"(r0), "=r"(r1) : "r"(a))
#define MMA16816(c, a, b) \
    asm volatile("mma.sync.aligned.m16n8k16.row.col.f32.bf16.bf16.f32 " \
                 "{%0,%1,%2,%3}, {%4,%5,%6,%7}, {%8,%9}, {%0,%1,%2,%3};" \
                 : "+f"((c)[0]), "+f"((c)[1]), "+f"((c)[2]), "+f"((c)[3]) \
                 : "r"((a)[0]), "r"((a)[1]), "r"((a)[2]), "r"((a)[3]), \
                   "r"((b)[0]), "r"((b)[1]))

__device__ __forceinline__ void acc_h4(float4& a, uint2 u) {
    float2 f0 = __half22float2(*reinterpret_cast<__half2*>(&u.x));
    float2 f1 = __half22float2(*reinterpret_cast<__half2*>(&u.y));
    a.x += f0.x; a.y += f0.y; a.z += f1.x; a.w += f1.y;
}

// ---------------- init: zero degrees + lookback flags + dtype detect -------
__global__ void init_kernel(const int* e32) {
    int i = blockIdx.x * blockDim.x + threadIdx.x;
    if (i < N_NODES) g_degi[i] = 0;
    if (i < SCAN_NB) g_lb[i] = 0u;
    if (i == 0) {
        int is64 = 1;
        #pragma unroll
        for (int k = 0; k < 32; ++k)
            if (e32[2 * k + 1] != 0) { is64 = 0; break; }
        g_is64 = is64;
    }
}

// ---------------- degree histogram + W hi/lo split (merged) ----------------
__global__ void deg_kernel(const void* __restrict__ edges,
                           const float* __restrict__ W1,
                           const float* __restrict__ W2) {
    int e = blockIdx.x * blockDim.x + threadIdx.x;
    if (e < F * F) {                       // W1 split/transpose
        int k = e >> 7, n = e & 127;
        float v = W1[e];
        __nv_bfloat16 h = __float2bfloat16(v);
        g_b1hi[n * F + k] = h;
        g_b1lo[n * F + k] = __float2bfloat16(v - __bfloat162float(h));
    } else if (e < F * F + F * NOUT2) {    // W2 split/transpose
        int q = e - F * F;
        int k = q >> 5, n = q & 31;
        float v = W2[q];
        __nv_bfloat16 h = __float2bfloat16(v);
        g_b2hi[n * F + k] = h;
        g_b2lo[n * F + k] = __float2bfloat16(v - __bfloat162float(h));
    }
    if (e >= NE) return;
    int d;
    if (g_is64) d = (int)((const long long*)edges)[NE + e];
    else        d = ((const int*)edges)[NE + e];
    atomicAdd(&g_degi[d], 1);
}

// ---------------- single-kernel scan with decoupled lookback ---------------
// 196 blocks, all co-resident. Publish (flag|aggregate), then threads
// t < blockIdx spin on predecessors in parallel and block-reduce.
__global__ void scanlb_kernel() {
    __shared__ int wred[8];
    __shared__ int wscn[8];
    __shared__ int base_sh;
    int b = blockIdx.x, t = threadIdx.x;
    int lane = t & 31, warp = t >> 5;
    int i = b * SCAN_BS + t;
    int v = (i < N_NODES) ? g_degi[i] : 0;

    // warp inclusive scan
    int s = v;
    #pragma unroll
    for (int off = 1; off < 32; off <<= 1) {
        int u = __shfl_up_sync(0xffffffffu, s, off);
        if (lane >= off) s += u;
    }
    if (lane == 31) wred[warp] = s;
    __syncthreads();
    if (t < 8) {
        int ws = wred[t];
        #pragma unroll
        for (int off = 1; off < 8; off <<= 1) {
            int u = __shfl_up_sync(0xffu, ws, off);
            if ((int)t >= off) ws += u;
        }
        wscn[t] = ws;                                   // inclusive warp-total scan
        if (t == 7) atomicExch(&g_lb[b], LBFLAG | (unsigned)ws);  // publish aggregate
    }
    __syncthreads();

    // parallel lookback
    int contrib = 0;
    if (t < b) {
        unsigned f;
        do { f = atomicAdd(&g_lb[t], 0u); } while (!(f & LBFLAG));
        contrib = (int)(f & ~LBFLAG);
    }
    #pragma unroll
    for (int off = 16; off > 0; off >>= 1)
        contrib += __shfl_down_sync(0xffffffffu, contrib, off);
    if (lane == 0) wred[warp] = contrib;
    __syncthreads();
    if (t == 0) {
        int base = 0;
        #pragma unroll
        for (int k = 0; k < 8; ++k) base += wred[k];
        base_sh = base;
        if (b == 0) g_rowptr[N_NODES] = NE;
    }
    __syncthreads();

    int excl = base_sh + (warp > 0 ? wscn[warp - 1] : 0) + (s - v);
    if (i < N_NODES) { g_rowptr[i] = excl; g_cur[i] = excl; }
}

// ---------------- CSR fill --------------------------------------------------
__global__ void fill_kernel(const void* __restrict__ edges) {
    int e = blockIdx.x * blockDim.x + threadIdx.x;
    if (e >= NE) return;
    int s, d;
    if (g_is64) {
        s = (int)((const long long*)edges)[e];
        d = (int)((const long long*)edges)[NE + e];
    } else {
        s = ((const int*)edges)[e];
        d = ((const int*)edges)[NE + e];
    }
    int pos = atomicAdd(&g_cur[d], 1);
    g_csr[pos] = s;
}

// ---------------- mma.sync GEMM: Yh = A @ B^T (fp16 out) -------------------
// LAYER 1: A staged from fp32 x with inline hi/lo split.
// LAYER 2: A staged from g_h1hi/g_h1lo.
template<int NCOLS, int LAYER>
__global__ __launch_bounds__(256) void gemm_mma_kernel(const float* __restrict__ x) {
    constexpr int ROWS = 64;
    constexpr int SROW = 136;
    constexpr int A_BYTES = ROWS * SROW * 2;
    constexpr int B_BYTES = NCOLS * SROW * 2;
    constexpr int OF_AHI = 0;
    constexpr int OF_ALO = A_BYTES;
    constexpr int OF_BHI = 2 * A_BYTES;
    constexpr int OF_BLO = OF_BHI + B_BYTES;
    constexpr int N8  = NCOLS / 32;
    constexpr int WNT = NCOLS / 4;
    constexpr int CS  = NCOLS + 4;

    const __nv_bfloat16* Bhi = (LAYER == 1) ? g_b1hi : g_b2hi;
    const __nv_bfloat16* Blo = (LAYER == 1) ? g_b1lo : g_b2lo;
    __half* Yh = (LAYER == 1) ? g_y1h : g_y2h;

    extern __shared__ char smem[];
    float* Csm = (float*)smem;
    uint32_t sb = smem_u32(smem);

    int t = threadIdx.x, lane = t & 31, wid = t >> 5;
    int row0 = blockIdx.x * ROWS;

    if constexpr (LAYER == 1) {
        // stage A from fp32 x, splitting to hi/lo on the fly
        for (int i = t; i < ROWS * 32; i += 256) {
            int r = i >> 5, c4 = i & 31;              // c4: float4 index
            int gr = row0 + r;
            float4 v = make_float4(0.f, 0.f, 0.f, 0.f);
            if (gr < N_NODES) v = ((const float4*)(x + (size_t)gr * F))[c4];
            __nv_bfloat162 h0 = __floats2bfloat162_rn(v.x, v.y);
            __nv_bfloat162 h1 = __floats2bfloat162_rn(v.z, v.w);
            __nv_bfloat162 l0 = __floats2bfloat162_rn(v.x - __low2float(h0),
                                                      v.y - __high2float(h0));
            __nv_bfloat162 l1 = __floats2bfloat162_rn(v.z - __low2float(h1),
                                                      v.w - __high2float(h1));
            uint2 uh, ul;
            uh.x = *reinterpret_cast<uint32_t*>(&h0);
            uh.y = *reinterpret_cast<uint32_t*>(&h1);
            ul.x = *reinterpret_cast<uint32_t*>(&l0);
            ul.y = *reinterpret_cast<uint32_t*>(&l1);
            *(uint2*)(smem + OF_AHI + r * (SROW * 2) + c4 * 8) = uh;
            *(uint2*)(smem + OF_ALO + r * (SROW * 2) + c4 * 8) = ul;
        }
    } else {
        for (int i = t; i < ROWS * 16; i += 256) {
            int r = i >> 4, c = (i & 15) * 8;
            int gr = row0 + r;
            uint4 vh = make_uint4(0, 0, 0, 0), vl = make_uint4(0, 0, 0, 0);
            if (gr < N_NODES) {
                vh = *(const uint4*)(g_h1hi + (size_t)gr * F + c);
                vl = *(const uint4*)(g_h1lo + (size_t)gr * F + c);
            }
            *(uint4*)(smem + OF_AHI + r * (SROW * 2) + c * 2) = vh;
            *(uint4*)(smem + OF_ALO + r * (SROW * 2) + c * 2) = vl;
        }
    }
    for (int i = t; i < NCOLS * 16; i += 256) {
        int r = i >> 4, c = (i & 15) * 8;
        *(uint4*)(smem + OF_BHI + r * (SROW * 2) + c * 2) =
            *(const uint4*)(Bhi + (size_t)r * F + c);
        *(uint4*)(smem + OF_BLO + r * (SROW * 2) + c * 2) =
            *(const uint4*)(Blo + (size_t)r * F + c);
    }
    __syncthreads();

    int wm = wid & 1, wn = wid >> 1;
    int m0 = wm * 32, n0 = wn * WNT;

    float acc[2][N8][4];
    #pragma unroll
    for (int mi = 0; mi < 2; ++mi)
        #pragma unroll
        for (int nj = 0; nj < N8; ++nj)
            #pragma unroll
            for (int q = 0; q < 4; ++q) acc[mi][nj][q] = 0.f;

    int lrow = lane & 7, lsub = lane >> 3;
    int aRow = lrow + (lsub & 1) * 8, aCol = (lsub >> 1) * 8;
    int bRow = lrow + (lsub >> 1) * 8, bCol = (lsub & 1) * 8;
    int l16 = lane & 15;
    int b2Row = l16 & 7, b2Col = (l16 >> 3) * 8;

    const int passA[3] = { OF_AHI, OF_AHI, OF_ALO };
    const int passB[3] = { OF_BHI, OF_BLO, OF_BHI };

    #pragma unroll
    for (int p = 0; p < 3; ++p) {
        uint32_t Ab = sb + passA[p], Bb = sb + passB[p];
        #pragma unroll
        for (int k = 0; k < 8; ++k) {
            int k0 = k * 16;
            uint32_t a[2][4];
            #pragma unroll
            for (int mi = 0; mi < 2; ++mi) {
                uint32_t ad = Ab + ((m0 + mi * 16 + aRow) * SROW + k0 + aCol) * 2;
                LDSM4(a[mi][0], a[mi][1], a[mi][2], a[mi][3], ad);
            }
            uint32_t b[N8][2];
            if constexpr (N8 == 1) {
                uint32_t bd = Bb + ((n0 + b2Row) * SROW + k0 + b2Col) * 2;
                LDSM2(b[0][0], b[0][1], bd);
            } else {
                #pragma unroll
                for (int nj2 = 0; nj2 < N8 / 2; ++nj2) {
                    uint32_t bd = Bb + ((n0 + nj2 * 16 + bRow) * SROW + k0 + bCol) * 2;
                    uint32_t r0, r1, r2, r3;
                    LDSM4(r0, r1, r2, r3, bd);
                    b[nj2 * 2][0] = r0; b[nj2 * 2][1] = r1;
                    b[nj2 * 2 + 1][0] = r2; b[nj2 * 2 + 1][1] = r3;
                }
            }
            #pragma unroll
            for (int mi = 0; mi < 2; ++mi)
                #pragma unroll
                for (int nj = 0; nj < N8; ++nj)
                    MMA16816(acc[mi][nj], a[mi], b[nj]);
        }
    }

    __syncthreads();

    int g = lane >> 2, tp = lane & 3;
    #pragma unroll
    for (int mi = 0; mi < 2; ++mi)
        #pragma unroll
        for (int nj = 0; nj < N8; ++nj) {
            int rr = m0 + mi * 16 + g;
            int cc = n0 + nj * 8 + tp * 2;
            Csm[rr * CS + cc]           = acc[mi][nj][0];
            Csm[rr * CS + cc + 1]       = acc[mi][nj][1];
            Csm[(rr + 8) * CS + cc]     = acc[mi][nj][2];
            Csm[(rr + 8) * CS + cc + 1] = acc[mi][nj][3];
        }
    __syncthreads();

    for (int i = t; i < ROWS * (NCOLS / 8); i += 256) {
        int r = i / (NCOLS / 8), c8 = (i % (NCOLS / 8)) * 8;
        int row = row0 + r;
        if (row < N_NODES) {
            float4 u = *(float4*)&Csm[r * CS + c8];
            float4 w = *(float4*)&Csm[r * CS + c8 + 4];
            __half2 p0 = __floats2half2_rn(u.x, u.y);
            __half2 p1 = __floats2half2_rn(u.z, u.w);
            __half2 p2 = __floats2half2_rn(w.x, w.y);
            __half2 p3 = __floats2half2_rn(w.z, w.w);
            uint4 o;
            o.x = *reinterpret_cast<uint32_t*>(&p0);
            o.y = *reinterpret_cast<uint32_t*>(&p1);
            o.z = *reinterpret_cast<uint32_t*>(&p2);
            o.w = *reinterpret_cast<uint32_t*>(&p3);
            *(uint4*)(Yh + (size_t)row * NCOLS + c8) = o;
        }
    }
}

// ---------------- agg1: h1 = leaky((sum_nbr y1 + y1)*rinv + b1) -> bf16 ----
__global__ void agg1_kernel(const float* __restrict__ b1g) {
    int w = (blockIdx.x * blockDim.x + threadIdx.x) >> 5;
    if (w >= N_NODES) return;
    int lane = threadIdx.x & 31;
    const uint2* Y = (const uint2*)g_y1h;

    float4 a0 = make_float4(0.f, 0.f, 0.f, 0.f);
    float4 a1 = a0, a2 = a0, a3 = a0;
    acc_h4(a0, Y[(size_t)w * 32 + lane]);   // self

    int beg = g_rowptr[w], end = g_rowptr[w + 1];
    int j = beg;
    for (; j + 4 <= end; j += 4) {
        int s0 = g_csr[j], s1 = g_csr[j + 1], s2 = g_csr[j + 2], s3 = g_csr[j + 3];
        acc_h4(a0, Y[(size_t)s0 * 32 + lane]);
        acc_h4(a1, Y[(size_t)s1 * 32 + lane]);
        acc_h4(a2, Y[(size_t)s2 * 32 + lane]);
        acc_h4(a3, Y[(size_t)s3 * 32 + lane]);
    }
    for (; j < end; ++j)
        acc_h4(a0, Y[(size_t)g_csr[j] * 32 + lane]);

    float rinv = 1.0f / (float)(end - beg + 1);
    float4 b = ((const float4*)b1g)[lane];
    float4 h;
    h.x = (a0.x + a1.x + a2.x + a3.x) * rinv + b.x;
    h.y = (a0.y + a1.y + a2.y + a3.y) * rinv + b.y;
    h.z = (a0.z + a1.z + a2.z + a3.z) * rinv + b.z;
    h.w = (a0.w + a1.w + a2.w + a3.w) * rinv + b.w;
    h.x = h.x >= 0.f ? h.x : 0.01f * h.x;
    h.y = h.y >= 0.f ? h.y : 0.01f * h.y;
    h.z = h.z >= 0.f ? h.z : 0.01f * h.z;
    h.w = h.w >= 0.f ? h.w : 0.01f * h.w;

    __nv_bfloat162 p0 = __floats2bfloat162_rn(h.x, h.y);
    __nv_bfloat162 p1 = __floats2bfloat162_rn(h.z, h.w);
    __nv_bfloat162 q0 = __floats2bfloat162_rn(h.x - __low2float(p0), h.y - __high2float(p0));
    __nv_bfloat162 q1 = __floats2bfloat162_rn(h.z - __low2float(p1), h.w - __high2float(p1));
    ((__nv_bfloat162*)g_h1hi)[(size_t)w * 64 + lane * 2]     = p0;
    ((__nv_bfloat162*)g_h1hi)[(size_t)w * 64 + lane * 2 + 1] = p1;
    ((__nv_bfloat162*)g_h1lo)[(size_t)w * 64 + lane * 2]     = q0;
    ((__nv_bfloat162*)g_h1lo)[(size_t)w * 64 + lane * 2 + 1] = q1;
}

// ---------------- agg2: out = (sum_nbr y2 + y2)*rinv + b2 ------------------
__global__ void agg2_kernel(const float* __restrict__ b2g,
                            float* __restrict__ out) {
    int gw = (blockIdx.x * blockDim.x + threadIdx.x) >> 5;
    int lane = threadIdx.x & 31;
    int node = gw * 4 + (lane >> 3);
    if (node >= N_NODES) return;
    int l8 = lane & 7;
    const uint2* Y = (const uint2*)g_y2h;

    float4 a0 = make_float4(0.f, 0.f, 0.f, 0.f);
    float4 a1 = a0, a2 = a0, a3 = a0;
    acc_h4(a0, Y[(size_t)node * 8 + l8]);   // self

    int beg = g_rowptr[node], end = g_rowptr[node + 1];
    int j = beg;
    for (; j + 4 <= end; j += 4) {
        int s0 = g_csr[j], s1 = g_csr[j + 1], s2 = g_csr[j + 2], s3 = g_csr[j + 3];
        acc_h4(a0, Y[(size_t)s0 * 8 + l8]);
        acc_h4(a1, Y[(size_t)s1 * 8 + l8]);
        acc_h4(a2, Y[(size_t)s2 * 8 + l8]);
        acc_h4(a3, Y[(size_t)s3 * 8 + l8]);
    }
    for (; j < end; ++j)
        acc_h4(a0, Y[(size_t)g_csr[j] * 8 + l8]);

    float rinv = 1.0f / (float)(end - beg + 1);
    float4 b = ((const float4*)b2g)[l8];
    float4 o;
    o.x = (a0.x + a1.x + a2.x + a3.x) * rinv + b.x;
    o.y = (a0.y + a1.y + a2.y + a3.y) * rinv + b.y;
    o.z = (a0.z + a1.z + a2.z + a3.z) * rinv + b.z;
    o.w = (a0.w + a1.w + a2.w + a3.w) * rinv + b.w;
    ((float4*)(out + (size_t)node * NOUT2))[l8] = o;
}

// ---------------- launch ----------------------------------------------------
extern "C" void kernel_launch(void* const* d_in, const int* in_sizes, int n_in,
                              void* d_out, int out_size) {
    const float* in_feat = (const float*)d_in[0];
    const void*  edges   = d_in[1];
    const float* W1      = (const float*)d_in[2];
    const float* b1      = (const float*)d_in[3];
    const float* W2      = (const float*)d_in[4];
    const float* b2      = (const float*)d_in[5];
    float* out = (float*)d_out;

    const int smem_g1 = 2 * (64 * 136 * 2) + 2 * (128 * 136 * 2);   // 104,448
    const int smem_g2 = 2 * (64 * 136 * 2) + 2 * (32 * 136 * 2);    //  52,224
    cudaFuncSetAttribute(gemm_mma_kernel<128, 1>,
                         cudaFuncAttributeMaxDynamicSharedMemorySize, smem_g1);
    cudaFuncSetAttribute(gemm_mma_kernel<32, 2>,
                         cudaFuncAttributeMaxDynamicSharedMemorySize, smem_g2);

    init_kernel<<<(N_NODES + 255) / 256, 256>>>((const int*)edges);
    deg_kernel<<<(NE + 255) / 256, 256>>>(edges, W1, W2);
    scanlb_kernel<<<SCAN_NB, SCAN_BS>>>();
    fill_kernel<<<(NE + 255) / 256, 256>>>(edges);

    const int GB = (N_NODES + 63) / 64;   // 782
    gemm_mma_kernel<128, 1><<<GB, 256, smem_g1>>>(in_feat);
    agg1_kernel<<<(N_NODES * 32 + 255) / 256, 256>>>(b1);
    gemm_mma_kernel<32, 2><<<GB, 256, smem_g2>>>(nullptr);
    agg2_kernel<<<((N_NODES + 3) / 4 * 32 + 255) / 256, 256>>>(b2, out);
}

// round 9
// speedup vs baseline: 2.0152x; 1.0724x over previous
#include <cuda_runtime.h>
#include <cuda_bf16.h>
#include <cuda_fp16.h>
#include <cstdint>

#define N_NODES 50000
#define F 128
#define NOUT2 32
#define NE 800000

#define SCAN_BS 256
#define SCAN_NB ((N_NODES + SCAN_BS - 1) / SCAN_BS)   // 196
#define LBFLAG 0x80000000u

// ---------------- scratch (device globals: no allocation allowed) ----------
__device__ __align__(16) __half g_y1h[N_NODES * F];      // x @ W1 (fp16)
__device__ __align__(16) __half g_y2h[N_NODES * NOUT2];  // h1 @ W2 (fp16)
__device__ __align__(16) __nv_bfloat16 g_h1hi[N_NODES * F];
__device__ __align__(16) __nv_bfloat16 g_h1lo[N_NODES * F];
__device__ __align__(16) __nv_bfloat16 g_b1hi[F * F];     // W1^T [n][k]
__device__ __align__(16) __nv_bfloat16 g_b1lo[F * F];
__device__ __align__(16) __nv_bfloat16 g_b2hi[NOUT2 * F]; // W2^T [n][k]
__device__ __align__(16) __nv_bfloat16 g_b2lo[NOUT2 * F];
__device__ int g_csr[NE];
__device__ int g_rowptr[N_NODES + 1];
__device__ int g_cur[N_NODES];
__device__ int g_degi[N_NODES];
__device__ unsigned g_lb[SCAN_NB];     // lookback aggregates (flag-packed)
__device__ int g_is64;

// ---------------- helpers ---------------------------------------------------
__device__ __forceinline__ uint32_t smem_u32(const void* p) {
    uint32_t a;
    asm("{ .reg .u64 t; cvta.to.shared.u64 t, %1; cvt.u32.u64 %0, t; }"
        : "=r"(a) : "l"(p));
    return a;
}
#define LDSM4(r0, r1, r2, r3, a) \
    asm volatile("ldmatrix.sync.aligned.m8n8.x4.shared.b16 {%0,%1,%2,%3}, [%4];" \
                 : "=r"(r0), "=r"(r1), "=r"(r2), "=r"(r3) : "r"(a))
#define LDSM2(r0, r1, a) \
    asm volatile("ldmatrix.sync.aligned.m8n8.x2.shared.b16 {%0,%1}, [%2];" \
                 : "=r"(r0), "=r"(r1) : "r"(a))
#define MMA16816(c, a, b) \
    asm volatile("mma.sync.aligned.m16n8k16.row.col.f32.bf16.bf16.f32 " \
                 "{%0,%1,%2,%3}, {%4,%5,%6,%7}, {%8,%9}, {%0,%1,%2,%3};" \
                 : "+f"((c)[0]), "+f"((c)[1]), "+f"((c)[2]), "+f"((c)[3]) \
                 : "r"((a)[0]), "r"((a)[1]), "r"((a)[2]), "r"((a)[3]), \
                   "r"((b)[0]), "r"((b)[1]))

__device__ __forceinline__ void acc_h4(float4& a, uint2 u) {
    float2 f0 = __half22float2(*reinterpret_cast<__half2*>(&u.x));
    float2 f1 = __half22float2(*reinterpret_cast<__half2*>(&u.y));
    a.x += f0.x; a.y += f0.y; a.z += f1.x; a.w += f1.y;
}

// ---------------- init: zero deg + lb flags + dtype detect + W split -------
__global__ void init_kernel(const int* e32,
                            const float* __restrict__ W1,
                            const float* __restrict__ W2) {
    int i = blockIdx.x * blockDim.x + threadIdx.x;
    if (i < N_NODES) g_degi[i] = 0;
    if (i < SCAN_NB) g_lb[i] = 0u;
    if (i < F * F) {                       // W1 split/transpose
        int k = i >> 7, n = i & 127;
        float v = W1[i];
        __nv_bfloat16 h = __float2bfloat16(v);
        g_b1hi[n * F + k] = h;
        g_b1lo[n * F + k] = __float2bfloat16(v - __bfloat162float(h));
    } else if (i < F * F + F * NOUT2) {    // W2 split/transpose
        int q = i - F * F;
        int k = q >> 5, n = q & 31;
        float v = W2[q];
        __nv_bfloat16 h = __float2bfloat16(v);
        g_b2hi[n * F + k] = h;
        g_b2lo[n * F + k] = __float2bfloat16(v - __bfloat162float(h));
    }
    if (i == 0) {
        int is64 = 1;
        #pragma unroll
        for (int k = 0; k < 32; ++k)
            if (e32[2 * k + 1] != 0) { is64 = 0; break; }
        g_is64 = is64;
    }
}

// ---------------- degree histogram -----------------------------------------
__global__ void deg_kernel(const void* __restrict__ edges) {
    int e = blockIdx.x * blockDim.x + threadIdx.x;
    if (e >= NE) return;
    int d;
    if (g_is64) d = (int)((const long long*)edges)[NE + e];
    else        d = ((const int*)edges)[NE + e];
    atomicAdd(&g_degi[d], 1);
}

// ---------------- single-kernel scan with decoupled lookback ---------------
__global__ void scanlb_kernel() {
    __shared__ int wred[8];
    __shared__ int wscn[8];
    __shared__ int base_sh;
    int b = blockIdx.x, t = threadIdx.x;
    int lane = t & 31, warp = t >> 5;
    int i = b * SCAN_BS + t;
    int v = (i < N_NODES) ? g_degi[i] : 0;

    int s = v;
    #pragma unroll
    for (int off = 1; off < 32; off <<= 1) {
        int u = __shfl_up_sync(0xffffffffu, s, off);
        if (lane >= off) s += u;
    }
    if (lane == 31) wred[warp] = s;
    __syncthreads();
    if (t < 8) {
        int ws = wred[t];
        #pragma unroll
        for (int off = 1; off < 8; off <<= 1) {
            int u = __shfl_up_sync(0xffu, ws, off);
            if ((int)t >= off) ws += u;
        }
        wscn[t] = ws;
        if (t == 7) atomicExch(&g_lb[b], LBFLAG | (unsigned)ws);
    }
    __syncthreads();

    int contrib = 0;
    if (t < b) {
        unsigned f;
        do { f = atomicAdd(&g_lb[t], 0u); } while (!(f & LBFLAG));
        contrib = (int)(f & ~LBFLAG);
    }
    #pragma unroll
    for (int off = 16; off > 0; off >>= 1)
        contrib += __shfl_down_sync(0xffffffffu, contrib, off);
    if (lane == 0) wred[warp] = contrib;
    __syncthreads();
    if (t == 0) {
        int base = 0;
        #pragma unroll
        for (int k = 0; k < 8; ++k) base += wred[k];
        base_sh = base;
        if (b == 0) g_rowptr[N_NODES] = NE;
    }
    __syncthreads();

    int excl = base_sh + (warp > 0 ? wscn[warp - 1] : 0) + (s - v);
    if (i < N_NODES) { g_rowptr[i] = excl; g_cur[i] = excl; }
}

// ---------------- CSR fill --------------------------------------------------
__global__ void fill_kernel(const void* __restrict__ edges) {
    int e = blockIdx.x * blockDim.x + threadIdx.x;
    if (e >= NE) return;
    int s, d;
    if (g_is64) {
        s = (int)((const long long*)edges)[e];
        d = (int)((const long long*)edges)[NE + e];
    } else {
        s = ((const int*)edges)[e];
        d = ((const int*)edges)[NE + e];
    }
    int pos = atomicAdd(&g_cur[d], 1);
    g_csr[pos] = s;
}

// ---------------- mma.sync GEMM: Yh = A @ B^T (fp16 out) -------------------
template<int NCOLS, int LAYER>
__global__ __launch_bounds__(256) void gemm_mma_kernel(const float* __restrict__ x) {
    constexpr int ROWS = 64;
    constexpr int SROW = 136;
    constexpr int A_BYTES = ROWS * SROW * 2;
    constexpr int B_BYTES = NCOLS * SROW * 2;
    constexpr int OF_AHI = 0;
    constexpr int OF_ALO = A_BYTES;
    constexpr int OF_BHI = 2 * A_BYTES;
    constexpr int OF_BLO = OF_BHI + B_BYTES;
    constexpr int N8  = NCOLS / 32;
    constexpr int WNT = NCOLS / 4;
    constexpr int CS  = NCOLS + 4;

    const __nv_bfloat16* Bhi = (LAYER == 1) ? g_b1hi : g_b2hi;
    const __nv_bfloat16* Blo = (LAYER == 1) ? g_b1lo : g_b2lo;
    __half* Yh = (LAYER == 1) ? g_y1h : g_y2h;

    extern __shared__ char smem[];
    float* Csm = (float*)smem;
    uint32_t sb = smem_u32(smem);

    int t = threadIdx.x, lane = t & 31, wid = t >> 5;
    int row0 = blockIdx.x * ROWS;

    if constexpr (LAYER == 1) {
        for (int i = t; i < ROWS * 32; i += 256) {
            int r = i >> 5, c4 = i & 31;
            int gr = row0 + r;
            float4 v = make_float4(0.f, 0.f, 0.f, 0.f);
            if (gr < N_NODES) v = ((const float4*)(x + (size_t)gr * F))[c4];
            __nv_bfloat162 h0 = __floats2bfloat162_rn(v.x, v.y);
            __nv_bfloat162 h1 = __floats2bfloat162_rn(v.z, v.w);
            __nv_bfloat162 l0 = __floats2bfloat162_rn(v.x - __low2float(h0),
                                                      v.y - __high2float(h0));
            __nv_bfloat162 l1 = __floats2bfloat162_rn(v.z - __low2float(h1),
                                                      v.w - __high2float(h1));
            uint2 uh, ul;
            uh.x = *reinterpret_cast<uint32_t*>(&h0);
            uh.y = *reinterpret_cast<uint32_t*>(&h1);
            ul.x = *reinterpret_cast<uint32_t*>(&l0);
            ul.y = *reinterpret_cast<uint32_t*>(&l1);
            *(uint2*)(smem + OF_AHI + r * (SROW * 2) + c4 * 8) = uh;
            *(uint2*)(smem + OF_ALO + r * (SROW * 2) + c4 * 8) = ul;
        }
    } else {
        for (int i = t; i < ROWS * 16; i += 256) {
            int r = i >> 4, c = (i & 15) * 8;
            int gr = row0 + r;
            uint4 vh = make_uint4(0, 0, 0, 0), vl = make_uint4(0, 0, 0, 0);
            if (gr < N_NODES) {
                vh = *(const uint4*)(g_h1hi + (size_t)gr * F + c);
                vl = *(const uint4*)(g_h1lo + (size_t)gr * F + c);
            }
            *(uint4*)(smem + OF_AHI + r * (SROW * 2) + c * 2) = vh;
            *(uint4*)(smem + OF_ALO + r * (SROW * 2) + c * 2) = vl;
        }
    }
    for (int i = t; i < NCOLS * 16; i += 256) {
        int r = i >> 4, c = (i & 15) * 8;
        *(uint4*)(smem + OF_BHI + r * (SROW * 2) + c * 2) =
            *(const uint4*)(Bhi + (size_t)r * F + c);
        *(uint4*)(smem + OF_BLO + r * (SROW * 2) + c * 2) =
            *(const uint4*)(Blo + (size_t)r * F + c);
    }
    __syncthreads();

    int wm = wid & 1, wn = wid >> 1;
    int m0 = wm * 32, n0 = wn * WNT;

    float acc[2][N8][4];
    #pragma unroll
    for (int mi = 0; mi < 2; ++mi)
        #pragma unroll
        for (int nj = 0; nj < N8; ++nj)
            #pragma unroll
            for (int q = 0; q < 4; ++q) acc[mi][nj][q] = 0.f;

    int lrow = lane & 7, lsub = lane >> 3;
    int aRow = lrow + (lsub & 1) * 8, aCol = (lsub >> 1) * 8;
    int bRow = lrow + (lsub >> 1) * 8, bCol = (lsub & 1) * 8;
    int l16 = lane & 15;
    int b2Row = l16 & 7, b2Col = (l16 >> 3) * 8;

    const int passA[3] = { OF_AHI, OF_AHI, OF_ALO };
    const int passB[3] = { OF_BHI, OF_BLO, OF_BHI };

    #pragma unroll
    for (int p = 0; p < 3; ++p) {
        uint32_t Ab = sb + passA[p], Bb = sb + passB[p];
        #pragma unroll
        for (int k = 0; k < 8; ++k) {
            int k0 = k * 16;
            uint32_t a[2][4];
            #pragma unroll
            for (int mi = 0; mi < 2; ++mi) {
                uint32_t ad = Ab + ((m0 + mi * 16 + aRow) * SROW + k0 + aCol) * 2;
                LDSM4(a[mi][0], a[mi][1], a[mi][2], a[mi][3], ad);
            }
            uint32_t b[N8][2];
            if constexpr (N8 == 1) {
                uint32_t bd = Bb + ((n0 + b2Row) * SROW + k0 + b2Col) * 2;
                LDSM2(b[0][0], b[0][1], bd);
            } else {
                #pragma unroll
                for (int nj2 = 0; nj2 < N8 / 2; ++nj2) {
                    uint32_t bd = Bb + ((n0 + nj2 * 16 + bRow) * SROW + k0 + bCol) * 2;
                    uint32_t r0, r1, r2, r3;
                    LDSM4(r0, r1, r2, r3, bd);
                    b[nj2 * 2][0] = r0; b[nj2 * 2][1] = r1;
                    b[nj2 * 2 + 1][0] = r2; b[nj2 * 2 + 1][1] = r3;
                }
            }
            #pragma unroll
            for (int mi = 0; mi < 2; ++mi)
                #pragma unroll
                for (int nj = 0; nj < N8; ++nj)
                    MMA16816(acc[mi][nj], a[mi], b[nj]);
        }
    }

    __syncthreads();

    int g = lane >> 2, tp = lane & 3;
    #pragma unroll
    for (int mi = 0; mi < 2; ++mi)
        #pragma unroll
        for (int nj = 0; nj < N8; ++nj) {
            int rr = m0 + mi * 16 + g;
            int cc = n0 + nj * 8 + tp * 2;
            Csm[rr * CS + cc]           = acc[mi][nj][0];
            Csm[rr * CS + cc + 1]       = acc[mi][nj][1];
            Csm[(rr + 8) * CS + cc]     = acc[mi][nj][2];
            Csm[(rr + 8) * CS + cc + 1] = acc[mi][nj][3];
        }
    __syncthreads();

    for (int i = t; i < ROWS * (NCOLS / 8); i += 256) {
        int r = i / (NCOLS / 8), c8 = (i % (NCOLS / 8)) * 8;
        int row = row0 + r;
        if (row < N_NODES) {
            float4 u = *(float4*)&Csm[r * CS + c8];
            float4 w = *(float4*)&Csm[r * CS + c8 + 4];
            __half2 p0 = __floats2half2_rn(u.x, u.y);
            __half2 p1 = __floats2half2_rn(u.z, u.w);
            __half2 p2 = __floats2half2_rn(w.x, w.y);
            __half2 p3 = __floats2half2_rn(w.z, w.w);
            uint4 o;
            o.x = *reinterpret_cast<uint32_t*>(&p0);
            o.y = *reinterpret_cast<uint32_t*>(&p1);
            o.z = *reinterpret_cast<uint32_t*>(&p2);
            o.w = *reinterpret_cast<uint32_t*>(&p3);
            *(uint4*)(Yh + (size_t)row * NCOLS + c8) = o;
        }
    }
}

// ---------------- agg1: h1 = leaky((sum_nbr y1 + y1)*rinv + b1) -> bf16 ----
__global__ void agg1_kernel(const float* __restrict__ b1g) {
    int w = (blockIdx.x * blockDim.x + threadIdx.x) >> 5;
    if (w >= N_NODES) return;
    int lane = threadIdx.x & 31;
    const uint2* Y = (const uint2*)g_y1h;

    float4 a0 = make_float4(0.f, 0.f, 0.f, 0.f);
    float4 a1 = a0, a2 = a0, a3 = a0;
    acc_h4(a0, Y[(size_t)w * 32 + lane]);   // self

    int beg = g_rowptr[w], end = g_rowptr[w + 1];
    int j = beg;
    for (; j + 4 <= end; j += 4) {
        int s0 = g_csr[j], s1 = g_csr[j + 1], s2 = g_csr[j + 2], s3 = g_csr[j + 3];
        acc_h4(a0, Y[(size_t)s0 * 32 + lane]);
        acc_h4(a1, Y[(size_t)s1 * 32 + lane]);
        acc_h4(a2, Y[(size_t)s2 * 32 + lane]);
        acc_h4(a3, Y[(size_t)s3 * 32 + lane]);
    }
    for (; j < end; ++j)
        acc_h4(a0, Y[(size_t)g_csr[j] * 32 + lane]);

    float rinv = 1.0f / (float)(end - beg + 1);
    float4 b = ((const float4*)b1g)[lane];
    float4 h;
    h.x = (a0.x + a1.x + a2.x + a3.x) * rinv + b.x;
    h.y = (a0.y + a1.y + a2.y + a3.y) * rinv + b.y;
    h.z = (a0.z + a1.z + a2.z + a3.z) * rinv + b.z;
    h.w = (a0.w + a1.w + a2.w + a3.w) * rinv + b.w;
    h.x = h.x >= 0.f ? h.x : 0.01f * h.x;
    h.y = h.y >= 0.f ? h.y : 0.01f * h.y;
    h.z = h.z >= 0.f ? h.z : 0.01f * h.z;
    h.w = h.w >= 0.f ? h.w : 0.01f * h.w;

    __nv_bfloat162 p0 = __floats2bfloat162_rn(h.x, h.y);
    __nv_bfloat162 p1 = __floats2bfloat162_rn(h.z, h.w);
    __nv_bfloat162 q0 = __floats2bfloat162_rn(h.x - __low2float(p0), h.y - __high2float(p0));
    __nv_bfloat162 q1 = __floats2bfloat162_rn(h.z - __low2float(p1), h.w - __high2float(p1));
    ((__nv_bfloat162*)g_h1hi)[(size_t)w * 64 + lane * 2]     = p0;
    ((__nv_bfloat162*)g_h1hi)[(size_t)w * 64 + lane * 2 + 1] = p1;
    ((__nv_bfloat162*)g_h1lo)[(size_t)w * 64 + lane * 2]     = q0;
    ((__nv_bfloat162*)g_h1lo)[(size_t)w * 64 + lane * 2 + 1] = q1;
}

// ---------------- agg2: out = (sum_nbr y2 + y2)*rinv + b2 ------------------
__global__ void agg2_kernel(const float* __restrict__ b2g,
                            float* __restrict__ out) {
    int gw = (blockIdx.x * blockDim.x + threadIdx.x) >> 5;
    int lane = threadIdx.x & 31;
    int node = gw * 4 + (lane >> 3);
    if (node >= N_NODES) return;
    int l8 = lane & 7;
    const uint2* Y = (const uint2*)g_y2h;

    float4 a0 = make_float4(0.f, 0.f, 0.f, 0.f);
    float4 a1 = a0, a2 = a0, a3 = a0;
    acc_h4(a0, Y[(size_t)node * 8 + l8]);   // self

    int beg = g_rowptr[node], end = g_rowptr[node + 1];
    int j = beg;
    for (; j + 4 <= end; j += 4) {
        int s0 = g_csr[j], s1 = g_csr[j + 1], s2 = g_csr[j + 2], s3 = g_csr[j + 3];
        acc_h4(a0, Y[(size_t)s0 * 8 + l8]);
        acc_h4(a1, Y[(size_t)s1 * 8 + l8]);
        acc_h4(a2, Y[(size_t)s2 * 8 + l8]);
        acc_h4(a3, Y[(size_t)s3 * 8 + l8]);
    }
    for (; j < end; ++j)
        acc_h4(a0, Y[(size_t)g_csr[j] * 8 + l8]);

    float rinv = 1.0f / (float)(end - beg + 1);
    float4 b = ((const float4*)b2g)[l8];
    float4 o;
    o.x = (a0.x + a1.x + a2.x + a3.x) * rinv + b.x;
    o.y = (a0.y + a1.y + a2.y + a3.y) * rinv + b.y;
    o.z = (a0.z + a1.z + a2.z + a3.z) * rinv + b.z;
    o.w = (a0.w + a1.w + a2.w + a3.w) * rinv + b.w;
    ((float4*)(out + (size_t)node * NOUT2))[l8] = o;
}

// ---------------- launch ----------------------------------------------------
extern "C" void kernel_launch(void* const* d_in, const int* in_sizes, int n_in,
                              void* d_out, int out_size) {
    const float* in_feat = (const float*)d_in[0];
    const void*  edges   = d_in[1];
    const float* W1      = (const float*)d_in[2];
    const float* b1      = (const float*)d_in[3];
    const float* W2      = (const float*)d_in[4];
    const float* b2      = (const float*)d_in[5];
    float* out = (float*)d_out;

    const int smem_g1 = 2 * (64 * 136 * 2) + 2 * (128 * 136 * 2);   // 104,448
    const int smem_g2 = 2 * (64 * 136 * 2) + 2 * (32 * 136 * 2);    //  52,224
    cudaFuncSetAttribute(gemm_mma_kernel<128, 1>,
                         cudaFuncAttributeMaxDynamicSharedMemorySize, smem_g1);
    cudaFuncSetAttribute(gemm_mma_kernel<32, 2>,
                         cudaFuncAttributeMaxDynamicSharedMemorySize, smem_g2);

    // side stream + events for capture-safe fork/join (created per call; no
    // device memory involved, so allocation guards are unaffected)
    cudaStream_t s2;
    cudaEvent_t evFork, evJoin;
    cudaStreamCreateWithFlags(&s2, cudaStreamNonBlocking);
    cudaEventCreateWithFlags(&evFork, cudaEventDisableTiming);
    cudaEventCreateWithFlags(&evJoin, cudaEventDisableTiming);

    const int GB = (N_NODES + 63) / 64;   // 782

    // init feeds both chains
    init_kernel<<<(N_NODES + 255) / 256, 256>>>((const int*)edges, W1, W2);
    cudaEventRecord(evFork, 0);

    // chain B (side stream): GEMM1 — independent of CSR build
    cudaStreamWaitEvent(s2, evFork, 0);
    gemm_mma_kernel<128, 1><<<GB, 256, smem_g1, s2>>>(in_feat);
    cudaEventRecord(evJoin, s2);

    // chain A (legacy stream): CSR build
    deg_kernel<<<(NE + 255) / 256, 256>>>(edges);
    scanlb_kernel<<<SCAN_NB, SCAN_BS>>>();
    fill_kernel<<<(NE + 255) / 256, 256>>>(edges);

    // join: agg1 needs CSR (legacy) + y1 (side)
    cudaStreamWaitEvent(0, evJoin, 0);
    agg1_kernel<<<(N_NODES * 32 + 255) / 256, 256>>>(b1);
    gemm_mma_kernel<32, 2><<<GB, 256, smem_g2>>>(nullptr);
    agg2_kernel<<<((N_NODES + 3) / 4 * 32 + 255) / 256, 256>>>(b2, out);
}